// round 13
// baseline (speedup 1.0000x reference)
#include <cuda_runtime.h>
#include <cuda_bf16.h>
#include <cuda_fp8.h>
#include <cstdint>

// Problem constants
#define Hv 4096
#define Vv 32000
#define Mv 4096          // B*S tokens
#define Sv 512
#define NROWS 250        // fallback sum-exp rows; tcgen05 path uses 126
#define NTILE_TC 126     // V padded to 32256 = 126 * 256
#define IGNORE_INDEX (-100)
#define WSCALE 64.0f
#define WISCALE 0.015625f
#define NCLUSTERS 33     // 132 CTAs — proven single-wave packing
#define TOT_TILES (8 * NTILE_TC)   // 1008: tm fastest (8 of M=512), nt = t>>3

#if defined(__CUDA_ARCH_FEAT_SM103_ALL) || defined(__CUDA_ARCH_FEAT_SM100_ALL) || \
    (defined(__CUDA_ARCH_FAMILY_SPECIFIC__) && (__CUDA_ARCH_FAMILY_SPECIFIC__ >= 1000))
#define HAS_TCGEN05 1
#else
#define HAS_TCGEN05 0
#endif

// ---------------- device scratch ----------------
__device__ __align__(128) unsigned char g_W8[(size_t)252 * 32 * 16384];  // 132 MB (2 pad row-tiles)
__device__ __align__(128) unsigned char g_X8[(size_t)32 * 32 * 16384];   // 16 MB
__device__ float g_wsumP[(size_t)250 * Hv];
__device__ float g_wsum[Hv];
__device__ float g_tgt[Mv];
__device__ float g_xdw[Mv];
__device__ float g_sumexp[(size_t)NROWS * Mv];
__device__ float g_logp[Mv];
__device__ int g_fb;   // 1 -> tcgen05 unavailable, mma.sync fallback must run

// ---------------- generic helpers ----------------
__device__ __forceinline__ uint32_t smem_u32(const void* p) {
    return (uint32_t)__cvta_generic_to_shared(p);
}
__device__ __forceinline__ uint16_t cvt_e4m3x2(float lo, float hi) {
    uint16_t r;
    asm("cvt.rn.satfinite.e4m3x2.f32 %0, %1, %2;" : "=h"(r) : "f"(hi), "f"(lo));
    return r;
}

// fallback loader: 4 fp8 at (row, k) [k%4==0] -> 4 bf16 (scaled)
__device__ __forceinline__ uint2 ld_blk8(const unsigned char* base, int row, int k, float scale) {
    size_t tile = ((size_t)(row >> 7) * 32 + (k >> 7)) * 16384;
    int rr = row & 127, cc = k & 127;
    int chunk = rr * 128 + (cc >> 4) * 16;
    int sw = chunk ^ ((chunk >> 3) & 0x70);
    uint32_t v = *reinterpret_cast<const uint32_t*>(base + tile + (size_t)sw + (cc & 15));
    __nv_bfloat16 b[4];
#pragma unroll
    for (int i = 0; i < 4; i++) {
        __nv_fp8_storage_t fs = (__nv_fp8_storage_t)((v >> (8 * i)) & 0xFF);
        __half_raw hr = __nv_cvt_fp8_to_halfraw(fs, __NV_E4M3);
        float f = __half2float(*reinterpret_cast<__half*>(&hr)) * scale;
        b[i] = __float2bfloat16(f);
    }
    uint2 r;
    r.x = *reinterpret_cast<uint32_t*>(&b[0]);
    r.y = *reinterpret_cast<uint32_t*>(&b[2]);
    return r;
}

// ---------------- fallback-only W pass (runs only if g_fb == 1) ----------------
__global__ void __launch_bounds__(256) wpassfb_kernel(const float* __restrict__ W) {
    if (*(volatile int*)&g_fb == 0) return;
    __shared__ float cs[256][17];
    const int tid = threadIdx.x;
    const int vb = blockIdx.x;      // 0..249
    const int c16 = tid & 7;
    for (int kb = 0; kb < 32; ++kb) {
        const float* src = W + (size_t)vb * 128 * Hv + kb * 128;
        unsigned char* dst = g_W8 + ((size_t)(vb * 32 + kb)) * 16384;
        float s[16];
#pragma unroll
        for (int k = 0; k < 16; k++) s[k] = 0.f;
#pragma unroll
        for (int j = 0; j < 4; j++) {
            int r = (tid >> 3) + j * 32;
            const float4* p = reinterpret_cast<const float4*>(src + (size_t)r * Hv + c16 * 16);
            float v[16];
#pragma unroll
            for (int q = 0; q < 4; q++) {
                float4 f = p[q];
                v[q * 4 + 0] = f.x; v[q * 4 + 1] = f.y; v[q * 4 + 2] = f.z; v[q * 4 + 3] = f.w;
            }
#pragma unroll
            for (int k = 0; k < 16; k++) s[k] += v[k];
            uint16_t h[8];
#pragma unroll
            for (int q = 0; q < 8; q++)
                h[q] = cvt_e4m3x2(v[2 * q] * WSCALE, v[2 * q + 1] * WSCALE);
            uint4 u;
            u.x = (uint32_t)h[0] | ((uint32_t)h[1] << 16);
            u.y = (uint32_t)h[2] | ((uint32_t)h[3] << 16);
            u.z = (uint32_t)h[4] | ((uint32_t)h[5] << 16);
            u.w = (uint32_t)h[6] | ((uint32_t)h[7] << 16);
            int boff = r * 128 + c16 * 16;
            int sw = boff ^ ((boff >> 3) & 0x70);
            *reinterpret_cast<uint4*>(dst + sw) = u;
        }
#pragma unroll
        for (int k = 0; k < 16; k++) cs[tid][k] = s[k];
        __syncthreads();
        for (int step = 128; step >= 8; step >>= 1) {
            if (tid < step) {
#pragma unroll
                for (int k = 0; k < 16; k++) cs[tid][k] += cs[tid + step][k];
            }
            __syncthreads();
        }
        if (tid < 8) {
#pragma unroll
            for (int k = 0; k < 16; k++)
                g_wsumP[(size_t)vb * Hv + kb * 128 + tid * 16 + k] = cs[tid][k];
        }
        __syncthreads();
    }
}

// ---------------- x pass: fp32 -> blocked swizzled e4m3 ----------------
__global__ void __launch_bounds__(256) convx3_kernel(const float* __restrict__ X) {
    const int tid = threadIdx.x;
    const int kb = blockIdx.x;      // 0..31
    const int mb = blockIdx.y;      // 0..31
    const float* src = X + (size_t)mb * 128 * Hv + kb * 128;
    unsigned char* dst = g_X8 + ((size_t)(mb * 32 + kb)) * 16384;
    const int c16 = tid & 7;
#pragma unroll
    for (int j = 0; j < 4; j++) {
        int r = (tid >> 3) + j * 32;
        const float4* p = reinterpret_cast<const float4*>(src + (size_t)r * Hv + c16 * 16);
        float v[16];
#pragma unroll
        for (int q = 0; q < 4; q++) {
            float4 f = p[q];
            v[q * 4 + 0] = f.x; v[q * 4 + 1] = f.y; v[q * 4 + 2] = f.z; v[q * 4 + 3] = f.w;
        }
        uint16_t h[8];
#pragma unroll
        for (int q = 0; q < 8; q++)
            h[q] = cvt_e4m3x2(v[2 * q], v[2 * q + 1]);
        uint4 u;
        u.x = (uint32_t)h[0] | ((uint32_t)h[1] << 16);
        u.y = (uint32_t)h[2] | ((uint32_t)h[3] << 16);
        u.z = (uint32_t)h[4] | ((uint32_t)h[5] << 16);
        u.w = (uint32_t)h[6] | ((uint32_t)h[7] << 16);
        int boff = r * 128 + c16 * 16;
        int sw = boff ^ ((boff >> 3) & 0x70);
        *reinterpret_cast<uint4*>(dst + sw) = u;
    }
}

__global__ void wsum_reduce_kernel() {
    int h = blockIdx.x * blockDim.x + threadIdx.x;
    float s = 0.f;
    for (int seg = 0; seg < 250; seg++) s += g_wsumP[(size_t)seg * Hv + h];
    g_wsum[h] = s;
}

// ---------------- exact fp32 target logit + x.wsum ----------------
__global__ void target_kernel(const float* __restrict__ x, const float* __restrict__ W,
                              const int* __restrict__ tg) {
    int warp = threadIdx.x >> 5, lane = threadIdx.x & 31;
    int t = blockIdx.x * 8 + warp;
    int tv = tg[t];
    int safe = tv < 0 ? 0 : (tv >= Vv ? Vv - 1 : tv);
    const float4* xr = reinterpret_cast<const float4*>(x + (size_t)t * Hv);
    const float4* wr = reinterpret_cast<const float4*>(W + (size_t)safe * Hv);
    const float4* sr = reinterpret_cast<const float4*>(g_wsum);
    float d1 = 0.f, d2 = 0.f;
#pragma unroll 4
    for (int i = lane; i < Hv / 4; i += 32) {
        float4 a = xr[i], b = wr[i], c = sr[i];
        d1 += a.x * b.x + a.y * b.y + a.z * b.z + a.w * b.w;
        d2 += a.x * c.x + a.y * c.y + a.z * c.z + a.w * c.w;
    }
#pragma unroll
    for (int o = 16; o; o >>= 1) {
        d1 += __shfl_xor_sync(0xFFFFFFFFu, d1, o);
        d2 += __shfl_xor_sync(0xFFFFFFFFu, d2, o);
    }
    if (lane == 0) { g_tgt[t] = d1; g_xdw[t] = d2; }
}

// ---------------- reset: flag + W pad tiles only ----------------
__global__ void reset_kernel() {
    long tid0 = (long)blockIdx.x * blockDim.x + threadIdx.x;
    uint4* pad = reinterpret_cast<uint4*>(g_W8 + (size_t)250 * 32 * 16384);
    if (tid0 < (long)(2 * 32 * 16384 / 16)) pad[tid0] = make_uint4(0, 0, 0, 0);
    if (tid0 == 0) g_fb = 0;
}

// ============================================================================
// tcgen05 FP8 persistent path (arch-specific variant only)
// Round-10 proven pipeline + in-kernel W conversion in epilogue-warp slack.
// ============================================================================
#define NSTAGE 4
#define STAGE_BYTES 32768         // A 16K + B 16K
#define SMEM_HDR 4096             // barriers [8,120) + epi_part [256,2304); DATA at 4096
#define GEMM_SMEM (SMEM_HDR + NSTAGE * STAGE_BYTES)
#define GTHREADS 320              // warps 0-7 epilogue+convert, 8 producer, 9 mma/relay

#if HAS_TCGEN05
__device__ __forceinline__ uint32_t elect_one() {
    uint32_t pred;
    asm volatile("{\n\t.reg .pred p;\n\telect.sync _|p, 0xFFFFFFFF;\n\tselp.b32 %0, 1, 0, p;\n\t}"
                 : "=r"(pred));
    return pred;
}
__device__ __forceinline__ void mbar_init(uint32_t a, uint32_t cnt) {
    asm volatile("mbarrier.init.shared.b64 [%0], %1;" :: "r"(a), "r"(cnt) : "memory");
}
__device__ __forceinline__ void mbar_expect_tx(uint32_t a, uint32_t tx) {
    asm volatile("mbarrier.arrive.expect_tx.shared.b64 _, [%0], %1;" :: "r"(a), "r"(tx) : "memory");
}
__device__ __forceinline__ void mbar_arrive(uint32_t a) {
    asm volatile("mbarrier.arrive.shared.b64 _, [%0];" :: "r"(a) : "memory");
}
__device__ __forceinline__ void mbar_arrive_rank(uint32_t a, uint32_t rank) {
    asm volatile("{\n\t.reg .b32 ra;\n\tmapa.shared::cluster.u32 ra, %0, %1;\n\t"
                 "mbarrier.arrive.shared::cluster.b64 _, [ra];\n\t}" :: "r"(a), "r"(rank) : "memory");
}
__device__ __forceinline__ void mbar_wait(uint32_t a, uint32_t parity) {
    asm volatile(
        "{\n\t.reg .pred P;\n"
        "WL%=:\n\t"
        "mbarrier.try_wait.parity.acquire.cta.shared::cta.b64 P, [%0], %1, 0x989680;\n\t"
        "@P bra WD%=;\n\t"
        "bra WL%=;\n"
        "WD%=:\n\t}"
        :: "r"(a), "r"(parity) : "memory");
}
__device__ __forceinline__ void bulk_g2s(uint32_t dst, const void* src, uint32_t bytes,
                                         uint32_t mbar) {
    asm volatile(
        "cp.async.bulk.shared::cluster.global.mbarrier::complete_tx::bytes [%0], [%1], %2, [%3];"
        :: "r"(dst), "l"(src), "r"(bytes), "r"(mbar) : "memory");
}
__device__ __forceinline__ void bulk_g2s_mc(uint32_t dst, const void* src, uint32_t bytes,
                                            uint32_t mbar, uint16_t mask) {
    asm volatile(
        "cp.async.bulk.shared::cluster.global.mbarrier::complete_tx::bytes.multicast::cluster "
        "[%0], [%1], %2, [%3], %4;"
        :: "r"(dst), "l"(src), "r"(bytes), "r"(mbar), "h"(mask) : "memory");
}
__device__ __forceinline__ void cluster_sync_() {
    asm volatile("barrier.cluster.arrive.aligned;" ::: "memory");
    asm volatile("barrier.cluster.wait.aligned;" ::: "memory");
}
__device__ __forceinline__ void tc_fence_after() {
    asm volatile("tcgen05.fence::after_thread_sync;" ::: "memory");
}
__device__ __forceinline__ void tc_fence_before() {
    asm volatile("tcgen05.fence::before_thread_sync;" ::: "memory");
}
__device__ __forceinline__ void tc_wait_ld() {
    asm volatile("tcgen05.wait::ld.sync.aligned;" ::: "memory");
}
__device__ __forceinline__ void tmem_alloc_cg2(uint32_t smem_addr, uint32_t ncols) {
    asm volatile("tcgen05.alloc.cta_group::2.sync.aligned.shared::cta.b32 [%0], %1;"
                 :: "r"(smem_addr), "r"(ncols) : "memory");
}
__device__ __forceinline__ void tmem_dealloc_cg2(uint32_t tmem, uint32_t ncols) {
    asm volatile("tcgen05.relinquish_alloc_permit.cta_group::2.sync.aligned;");
    asm volatile("tcgen05.dealloc.cta_group::2.sync.aligned.b32 %0, %1;" :: "r"(tmem), "r"(ncols));
}
__device__ __forceinline__ void mma_f8_ss_cg2(uint32_t d_tmem, uint64_t a_desc, uint64_t b_desc,
                                              uint32_t idesc, uint32_t en) {
    asm volatile(
        "{\n\t.reg .pred p;\n\t"
        "setp.ne.u32 p, %6, 0;\n\t"
        "tcgen05.mma.cta_group::2.kind::f8f6f4 [%0], %1, %2, %3, "
        "{%4, %4, %4, %4, %4, %4, %4, %4}, p;\n\t}"
        :: "r"(d_tmem), "l"(a_desc), "l"(b_desc), "r"(idesc),
           "r"(0u), "r"(0u), "r"(en)
        : "memory");
}
__device__ __forceinline__ void commit_mc_cg2(uint32_t mbar, uint16_t mask) {
    asm volatile(
        "tcgen05.commit.cta_group::2.mbarrier::arrive::one.shared::cluster.multicast::cluster.b64 [%0], %1;"
        :: "r"(mbar), "h"(mask) : "memory");
}
__device__ __forceinline__ void ldtm_x32(uint32_t* r, uint32_t addr) {
    asm volatile(
        "tcgen05.ld.sync.aligned.32x32b.x32.b32 "
        "{%0, %1, %2, %3, %4, %5, %6, %7, "
        " %8, %9, %10, %11, %12, %13, %14, %15, "
        " %16, %17, %18, %19, %20, %21, %22, %23, "
        " %24, %25, %26, %27, %28, %29, %30, %31}, [%32];"
        : "=r"(r[0]), "=r"(r[1]), "=r"(r[2]), "=r"(r[3]),
          "=r"(r[4]), "=r"(r[5]), "=r"(r[6]), "=r"(r[7]),
          "=r"(r[8]), "=r"(r[9]), "=r"(r[10]), "=r"(r[11]),
          "=r"(r[12]), "=r"(r[13]), "=r"(r[14]), "=r"(r[15]),
          "=r"(r[16]), "=r"(r[17]), "=r"(r[18]), "=r"(r[19]),
          "=r"(r[20]), "=r"(r[21]), "=r"(r[22]), "=r"(r[23]),
          "=r"(r[24]), "=r"(r[25]), "=r"(r[26]), "=r"(r[27]),
          "=r"(r[28]), "=r"(r[29]), "=r"(r[30]), "=r"(r[31])
        : "r"(addr));
}
__device__ __forceinline__ uint64_t make_desc(uint32_t addr) {
    const uint64_t base = (uint64_t(2) << 61) | (uint64_t(1) << 46) |
                          (uint64_t(64) << 32) | (uint64_t(1) << 16);
    return base | ((uint64_t)(addr >> 4) & 0x3FFF);
}

// Convert this cluster's B row-tiles for one nt (fp32 W -> x64 e4m3, swizzled)
// plus column partial sums. 64 units (2 rbB x 32 kt); CTA rank r takes units
// with (u & 3) == r; each of 8 epilogue warps takes 2 units. Pad rbB skipped.
// Boundary nts are duplicately converted by adjacent clusters: identical
// bytes, benign write races.
__device__ __forceinline__ void convert_nt_units(const float* __restrict__ W, int nt,
                                                 int r, int wid, int lane) {
#pragma unroll
    for (int mm = 0; mm < 2; ++mm) {
        const int u = r + 4 * (wid * 2 + mm);
        const int rbB = nt * 2 + (u >> 5);
        const int kt = u & 31;
        if (rbB >= 250) continue;
        const int colb = lane * 4;
        const float* src = W + (size_t)rbB * 128 * Hv + (size_t)kt * 128 + colb;
        unsigned char* dst = g_W8 + ((size_t)(rbB * 32 + kt)) * 16384;
        float s0 = 0.f, s1 = 0.f, s2 = 0.f, s3 = 0.f;
#pragma unroll 4
        for (int row = 0; row < 128; ++row) {
            float4 f = *reinterpret_cast<const float4*>(src + (size_t)row * Hv);
            s0 += f.x; s1 += f.y; s2 += f.z; s3 += f.w;
            uint16_t h0 = cvt_e4m3x2(f.x * WSCALE, f.y * WSCALE);
            uint16_t h1 = cvt_e4m3x2(f.z * WSCALE, f.w * WSCALE);
            uint32_t v = (uint32_t)h0 | ((uint32_t)h1 << 16);
            int boff = row * 128 + colb;
            int chunk = boff & ~15;
            int sw = (chunk ^ ((chunk >> 3) & 0x70)) | (colb & 15);
            *reinterpret_cast<uint32_t*>(dst + sw) = v;
        }
        float4 o; o.x = s0; o.y = s1; o.z = s2; o.w = s3;
        *reinterpret_cast<float4*>(&g_wsumP[(size_t)rbB * Hv + kt * 128 + colb]) = o;
    }
}
__device__ __forceinline__ void conv_publish(uint32_t conv_slot_addr) {
    // generic stores -> async proxy + gpu-scope release, then arrive on all 4 CTAs
    asm volatile("fence.proxy.async.global;" ::: "memory");
    asm volatile("fence.acq_rel.gpu;" ::: "memory");
#pragma unroll
    for (uint32_t rk = 0; rk < 4; ++rk) mbar_arrive_rank(conv_slot_addr, rk);
}
#endif // HAS_TCGEN05

// Persistent cluster (4,1,1) x 33 (132 CTAs). Per cluster tile: M=512 x N=256.
// TMEM ping-pong (D at cols 0/256); round-8 proven barrier protocol.
// NEW: epilogue warps convert nt+1's W tiles in their slack; producer gates
// each new nt's B TMAs on the intra-cluster CONV barrier (count 4, 2-slot ring).
__global__ void __launch_bounds__(GTHREADS, 1) __cluster_dims__(4, 1, 1)
gemm_kernel(const float* __restrict__ Wp) {
#if HAS_TCGEN05
    extern __shared__ char smem[];
    const uint32_t sb = smem_u32(smem);
    float* epi_part = reinterpret_cast<float*>(smem + 256);   // [2][8][32] = 2048B
    const int tid = threadIdx.x;
    const int wid = tid >> 5, lane = tid & 31;
    const int r = blockIdx.x & 3;          // cluster rank
    const int cid = blockIdx.x >> 2;       // cluster id 0..32
    const int p = r >> 1, prank = r & 1;   // pair, rank within pair

    const uint32_t FULL = sb + 8;          // 4 x 8B
    const uint32_t EMPTY = sb + 40;        // 4 x 8B
    const uint32_t TFULL = sb + 72;        // 2 x 8B
    const uint32_t TEPI = sb + 88;         // 2 x 8B
    const uint32_t CONV = sb + 104;        // 2 x 8B (W conversion ready, count 4)
    const uint32_t DATA = sb + SMEM_HDR;

    const int lo = (cid * TOT_TILES) / NCLUSTERS;
    const int hi = ((cid + 1) * TOT_TILES) / NCLUSTERS;
    const int ntl = hi - lo;
    const int nt0 = lo >> 3;
    const int ntLast = (hi - 1) >> 3;

    if (wid == 9) tmem_alloc_cg2(sb, 512);
    if (tid == 0) {
#pragma unroll
        for (int s = 0; s < NSTAGE; s++) {
            mbar_init(FULL + 8 * s, prank ? 1u : 2u);
            mbar_init(EMPTY + 8 * s, 2u);   // commits from BOTH pair leaders (0xF)
        }
        mbar_init(TFULL + 0, 1u);
        mbar_init(TFULL + 8, 1u);
        mbar_init(TEPI + 0, 2u);
        mbar_init(TEPI + 8, 2u);
        mbar_init(CONV + 0, 4u);
        mbar_init(CONV + 8, 4u);
    }
    __syncthreads();
    uint32_t tmem;
    asm volatile("ld.shared.b32 %0, [%1];" : "=r"(tmem) : "r"(sb));
    cluster_sync_();

    const uint16_t pair_mask = (p == 0) ? 0x3 : 0xC;

    if (wid == 8) {
        // ---- producer: elected thread streams A + (rank<2) multicast B ----
        if (elect_one()) {
            const uint16_t bmask = prank ? 0xA : 0x5;   // {1,3} : {0,2}
            int git = 0;
            int curNt = -1;
            for (int lt = 0; lt < ntl; ++lt) {
                const int t = lo + lt;
                const int tm = t & 7, nt = t >> 3;
                if (nt != curNt) {
                    curNt = nt;
                    const int j = nt - nt0;
                    mbar_wait(CONV + 8 * (j & 1), (j >> 1) & 1);
                    asm volatile("fence.acq_rel.gpu;" ::: "memory");
                    asm volatile("fence.proxy.async.global;" ::: "memory");
                }
                const int rbA = tm * 4 + r;            // A row-tile for this CTA
                const int rbB = nt * 2 + prank;        // B row-tile (ranks 0,1 load)
                for (int it = 0; it < 32; ++it, ++git) {
                    const int slot = git & (NSTAGE - 1);
                    const int u = git >> 2;
                    if (git >= NSTAGE) mbar_wait(EMPTY + 8 * slot, (u + 1) & 1);
                    const uint32_t fb = FULL + 8 * slot;
                    mbar_expect_tx(fb, STAGE_BYTES);
                    const uint32_t d = DATA + slot * STAGE_BYTES;
                    bulk_g2s(d, g_X8 + ((size_t)(rbA * 32 + it)) * 16384, 16384, fb);
                    if (r < 2)
                        bulk_g2s_mc(d + 16384, g_W8 + ((size_t)(rbB * 32 + it)) * 16384,
                                    16384, fb, bmask);
                }
            }
        }
    } else if (wid == 9) {
        if (prank == 1) {
            // ---- relay: forward local stage readiness to pair leader ----
            if (lane == 0) {
                int git = 0;
                for (int lt = 0; lt < ntl; ++lt)
                    for (int it = 0; it < 32; ++it, ++git) {
                        const int slot = git & (NSTAGE - 1);
                        mbar_wait(FULL + 8 * slot, (git >> 2) & 1);
                        mbar_arrive_rank(FULL + 8 * slot, (uint32_t)(r - 1));
                    }
            }
        } else {
            // ---- MMA issuer on pair leaders ----
            const uint32_t IDESC = (1u << 4) | ((256u / 8) << 17) | ((256u / 16) << 24);
            tc_fence_after();
            int git = 0;
            for (int lt = 0; lt < ntl; ++lt) {
                const int dbuf = lt & 1;
                if (lt >= 2) mbar_wait(TEPI + 8 * dbuf, ((lt >> 1) - 1) & 1);
                const uint32_t dt = tmem + dbuf * 256;
                for (int it = 0; it < 32; ++it, ++git) {
                    const int slot = git & (NSTAGE - 1);
                    mbar_wait(FULL + 8 * slot, (git >> 2) & 1);
                    if (elect_one()) {
                        const uint32_t base = DATA + slot * STAGE_BYTES;
                        uint64_t a = make_desc(base);
                        uint64_t b = make_desc(base + 16384);
#pragma unroll
                        for (int k = 0; k < 4; ++k) {
                            uint32_t en = (it | k) ? 1u : 0u;
                            mma_f8_ss_cg2(dt, a + k * 2, b + k * 2, IDESC, en);
                        }
                        commit_mc_cg2(EMPTY + 8 * slot, 0xF);
                    }
                }
                if (elect_one()) commit_mc_cg2(TFULL + 8 * dbuf, pair_mask);
            }
        }
    } else {
        // ---- epilogue + W-conversion: warps 0-7 (256 threads) ----
        // prologue: convert nt0, publish CONV slot 0
        convert_nt_units(Wp, nt0, r, wid, lane);
        asm volatile("bar.sync 1, 256;" ::: "memory");
        if (tid == 0) conv_publish(CONV + 0);

        const int cgrp = wid >> 2;          // col group: 0 -> [0,128), 1 -> [128,256)
        const int rowloc = (wid & 3) * 32 + lane;
        int prevNt = -1;
        for (int lt = 0; lt < ntl; ++lt) {
            const int t = lo + lt;
            const int tm = t & 7, nt = t >> 3;
            const int dbuf = lt & 1;
            if (nt != prevNt) {
                prevNt = nt;
                if (nt < ntLast) {
                    // convert next nt while MMA works on this one
                    convert_nt_units(Wp, nt + 1, r, wid, lane);
                    asm volatile("bar.sync 1, 256;" ::: "memory");
                    if (tid == 0) {
                        const int j = nt + 1 - nt0;
                        conv_publish(CONV + 8 * (j & 1));
                    }
                }
            }
            mbar_wait(TFULL + 8 * dbuf, (lt >> 1) & 1);
            tc_fence_after();
            const uint32_t dbase = tmem + dbuf * 256 + cgrp * 128;
            float s = 0.f;
#pragma unroll
            for (int c2 = 0; c2 < 2; ++c2) {
                uint32_t rg[2][32];
                ldtm_x32(rg[0], dbase + (c2 * 2) * 32);
                ldtm_x32(rg[1], dbase + (c2 * 2 + 1) * 32);
                tc_wait_ld();
#pragma unroll
                for (int i = 0; i < 32; ++i)
                    s += __expf(__uint_as_float(rg[0][i]) * WISCALE) +
                         __expf(__uint_as_float(rg[1][i]) * WISCALE);
            }
            tc_fence_before();
            epi_part[(dbuf * 8 + wid) * 32 + lane] = s;
            asm volatile("bar.sync 1, 256;" ::: "memory");
            if (wid < 4) {
                const int token = tm * 512 + p * 256 + prank * 128 + rowloc;
                float tot = s + epi_part[(dbuf * 8 + wid + 4) * 32 + lane];
                g_sumexp[(size_t)nt * Mv + token] = tot;
            }
            if (tid == 0) {
                if (prank == 0) mbar_arrive(TEPI + 8 * dbuf);
                else            mbar_arrive_rank(TEPI + 8 * dbuf, (uint32_t)(r - 1));
            }
        }
    }

    __syncthreads();
    if (wid == 9) tmem_dealloc_cg2(tmem, 512);
    cluster_sync_();
#else
    (void)Wp;
    if (threadIdx.x == 0 && blockIdx.x == 0) g_fb = 1;
#endif
}

// ============================================================================
// Fallback mma.sync GEMM (runs only if g_fb == 1); converts fp8 -> bf16 on load.
// ============================================================================
#define ASTRIDE 40

__global__ void __launch_bounds__(256) gemm_fb_kernel() {
    if (*(volatile int*)&g_fb == 0) return;
    __shared__ __nv_bfloat16 As[128 * ASTRIDE];
    __shared__ __nv_bfloat16 Bs[128 * ASTRIDE];
    __shared__ float rsum[2][128];

    const int tid = threadIdx.x;
    const int m0 = blockIdx.x * 128;
    const int n0 = blockIdx.y * 128;
    const int warp = tid >> 5, lane = tid & 31;
    const int mw = warp >> 1, nw = warp & 1;

    float acc[2][8][4];
#pragma unroll
    for (int a = 0; a < 2; a++)
#pragma unroll
        for (int b = 0; b < 8; b++)
#pragma unroll
            for (int c = 0; c < 4; c++) acc[a][b][c] = 0.f;

    uint2 pa[4], pb[4];
    auto loadG = [&](int kk) {
#pragma unroll
        for (int j = 0; j < 4; j++) {
            int i = tid + j * 256;
            int row = i >> 3, seg = i & 7;
            pa[j] = ld_blk8(g_X8, m0 + row, kk + seg * 4, 1.0f);
            pb[j] = ld_blk8(g_W8, n0 + row, kk + seg * 4, WISCALE);
        }
    };
    auto storeS = [&]() {
#pragma unroll
        for (int j = 0; j < 4; j++) {
            int i = tid + j * 256;
            int row = i >> 3, seg = i & 7;
            *reinterpret_cast<uint2*>(As + row * ASTRIDE + seg * 4) = pa[j];
            *reinterpret_cast<uint2*>(Bs + row * ASTRIDE + seg * 4) = pb[j];
        }
    };

    loadG(0);
    storeS();

    for (int it = 0; it < 128; ++it) {
        __syncthreads();
        if (it + 1 < 128) loadG((it + 1) * 32);

#pragma unroll
        for (int ks = 0; ks < 32; ks += 16) {
            uint32_t a[2][4];
#pragma unroll
            for (int mt = 0; mt < 2; mt++) {
                int row = mw * 32 + mt * 16 + (lane & 15);
                int col = ks + ((lane >> 4) << 3);
                uint32_t addr = smem_u32(As + row * ASTRIDE + col);
                asm volatile(
                    "ldmatrix.sync.aligned.m8n8.x4.shared.b16 {%0,%1,%2,%3}, [%4];"
                    : "=r"(a[mt][0]), "=r"(a[mt][1]), "=r"(a[mt][2]), "=r"(a[mt][3])
                    : "r"(addr));
            }
            uint32_t b[8][2];
#pragma unroll
            for (int np = 0; np < 4; np++) {
                int n = nw * 64 + np * 16 + (lane & 7) + ((lane >> 4) << 3);
                int kq = ks + (((lane >> 3) & 1) << 3);
                uint32_t addr = smem_u32(Bs + n * ASTRIDE + kq);
                asm volatile(
                    "ldmatrix.sync.aligned.m8n8.x4.shared.b16 {%0,%1,%2,%3}, [%4];"
                    : "=r"(b[2 * np][0]), "=r"(b[2 * np][1]),
                      "=r"(b[2 * np + 1][0]), "=r"(b[2 * np + 1][1])
                    : "r"(addr));
            }
#pragma unroll
            for (int mt = 0; mt < 2; mt++)
#pragma unroll
                for (int nt = 0; nt < 8; nt++) {
                    float* c = acc[mt][nt];
                    asm volatile(
                        "mma.sync.aligned.m16n8k16.row.col.f32.bf16.bf16.f32 "
                        "{%0,%1,%2,%3}, {%4,%5,%6,%7}, {%8,%9}, {%0,%1,%2,%3};"
                        : "+f"(c[0]), "+f"(c[1]), "+f"(c[2]), "+f"(c[3])
                        : "r"(a[mt][0]), "r"(a[mt][1]), "r"(a[mt][2]), "r"(a[mt][3]),
                          "r"(b[nt][0]), "r"(b[nt][1]));
                }
        }
        __syncthreads();
        if (it + 1 < 128) storeS();
    }

#pragma unroll
    for (int mt = 0; mt < 2; mt++) {
        float slo = 0.f, shi = 0.f;
#pragma unroll
        for (int nt = 0; nt < 8; nt++) {
            slo += __expf(acc[mt][nt][0]) + __expf(acc[mt][nt][1]);
            shi += __expf(acc[mt][nt][2]) + __expf(acc[mt][nt][3]);
        }
        slo += __shfl_xor_sync(0xFFFFFFFFu, slo, 1);
        slo += __shfl_xor_sync(0xFFFFFFFFu, slo, 2);
        shi += __shfl_xor_sync(0xFFFFFFFFu, shi, 1);
        shi += __shfl_xor_sync(0xFFFFFFFFu, shi, 2);
        if ((lane & 3) == 0) {
            int rr = mw * 32 + mt * 16 + (lane >> 2);
            rsum[nw][rr] = slo;
            rsum[nw][rr + 8] = shi;
        }
    }
    __syncthreads();
    if (tid < 128) {
        g_sumexp[(size_t)blockIdx.y * Mv + m0 + tid] = rsum[0][tid] + rsum[1][tid];
    }
}

// ---------------- per-token logp ----------------
__global__ void token_reduce_kernel(const int* __restrict__ tg) {
    int t = blockIdx.x * blockDim.x + threadIdx.x;
    if (t >= Mv) return;
    const int fb = g_fb;
    const int rows = fb ? NROWS : NTILE_TC;   // read exactly what was written
    float s = 0.f;
    for (int c = 0; c < rows; c++) s += g_sumexp[(size_t)c * Mv + t];
    if (fb == 0) s -= 256.0f;   // tcgen05 path: 256 zero-logit pad columns
    g_logp[t] = (tg[t] != IGNORE_INDEX) ? (g_tgt[t] - logf(s)) : 0.f;
}

// ---------------- final loss / outputs ----------------
__global__ void final_kernel(const int* __restrict__ tg, float* __restrict__ out) {
    __shared__ float red[256];
    __shared__ int redi[256];
    __shared__ float seq[8];
    __shared__ float xw[2];
    int tid = threadIdx.x;

    for (int s = 0; s < 8; s++) {
        float v = 0.f; int c = 0;
        for (int i = tid; i < Sv; i += 256) {
            int t = s * Sv + i;
            v += g_logp[t];
            c += (tg[t] != IGNORE_INDEX);
        }
        red[tid] = v; redi[tid] = c;
        __syncthreads();
        for (int o = 128; o; o >>= 1) {
            if (tid < o) { red[tid] += red[tid + o]; redi[tid] += redi[tid + o]; }
            __syncthreads();
        }
        if (tid == 0) seq[s] = red[0] / (float)redi[0];
        __syncthreads();
    }

    for (int h = 0; h < 2; h++) {
        float v = 0.f;
        for (int i = tid; i < 4 * Sv; i += 256) v += g_xdw[h * 4 * Sv + i];
        red[tid] = v;
        __syncthreads();
        for (int o = 128; o; o >>= 1) {
            if (tid < o) red[tid] += red[tid + o];
            __syncthreads();
        }
        if (tid == 0) xw[h] = red[0];
        __syncthreads();
    }

    if (tid == 0) {
        float loss = 0.f;
#pragma unroll
        for (int i = 0; i < 4; i++) {
            float z = 0.1f * (seq[i] - seq[4 + i]);
            float ls = fminf(z, 0.f) - log1pf(expf(-fabsf(z)));   // log_sigmoid(z)
            loss += -ls;
        }
        loss *= 0.25f;
        out[0] = loss;
#pragma unroll
        for (int i = 0; i < 8; i++) out[1 + i] = seq[i];
        const float denom = 4.0f * (float)Sv * (float)Vv;
        out[9] = xw[0] / denom;
        out[10] = xw[1] / denom;
        out[11] = 0.0f;
    }
}

// ---------------- launch ----------------
extern "C" void kernel_launch(void* const* d_in, const int* in_sizes, int n_in,
                              void* d_out, int out_size) {
    const float* x = nullptr;
    const float* W = nullptr;
    const int* tg = nullptr;
    for (int i = 0; i < n_in; i++) {
        if (in_sizes[i] == Vv * Hv) W = (const float*)d_in[i];
        else if (in_sizes[i] == Mv * Hv) x = (const float*)d_in[i];
        else if (in_sizes[i] == Mv) tg = (const int*)d_in[i];
    }
    float* out = (float*)d_out;

    cudaFuncSetAttribute(gemm_kernel, cudaFuncAttributeMaxDynamicSharedMemorySize, GEMM_SMEM);

    convx3_kernel<<<dim3(32, 32), 256>>>(x);               // 1
    reset_kernel<<<256, 256>>>();                          // 2
    gemm_kernel<<<4 * NCLUSTERS, GTHREADS, GEMM_SMEM>>>(W); // 3 (converts W in-kernel)
    wpassfb_kernel<<<250, 256>>>(W);                       // 4 (no-op if tcgen05 ran)
    gemm_fb_kernel<<<dim3(32, 250), 256>>>();              // 5 (no-op if tcgen05 ran)
    wsum_reduce_kernel<<<16, 256>>>();                     // 6
    target_kernel<<<512, 256>>>(x, W, tg);                 // 7
    token_reduce_kernel<<<32, 128>>>(tg);                  // 8
    final_kernel<<<1, 256>>>(tg, out);                     // 9
}

// round 14
// speedup vs baseline: 1.1585x; 1.1585x over previous
#include <cuda_runtime.h>
#include <cuda_bf16.h>
#include <cuda_fp8.h>
#include <cstdint>

// Problem constants
#define Hv 4096
#define Vv 32000
#define Mv 4096          // B*S tokens
#define Sv 512
#define NROWS 250        // fallback sum-exp rows; tcgen05 path uses 126
#define NTILE_TC 126     // V padded to 32256 = 126 * 256
#define IGNORE_INDEX (-100)
#define WSCALE 64.0f
#define WISCALE 0.015625f
#define NCLUSTERS 33     // 132 CTAs — proven single-wave packing
#define TOT_TILES (8 * NTILE_TC)   // 1008: tm fastest (8 of M=512), nt = t>>3

#if defined(__CUDA_ARCH_FEAT_SM103_ALL) || defined(__CUDA_ARCH_FEAT_SM100_ALL) || \
    (defined(__CUDA_ARCH_FAMILY_SPECIFIC__) && (__CUDA_ARCH_FAMILY_SPECIFIC__ >= 1000))
#define HAS_TCGEN05 1
#else
#define HAS_TCGEN05 0
#endif

// ---------------- device scratch ----------------
__device__ __align__(128) unsigned char g_W8[(size_t)252 * 32 * 16384];  // 132 MB (2 pad row-tiles)
__device__ __align__(128) unsigned char g_X8[(size_t)32 * 32 * 16384];   // 16 MB
__device__ float g_wsumP[(size_t)250 * Hv];
__device__ float g_wsum[Hv];
__device__ float g_tgt[Mv];
__device__ float g_xdw[Mv];
__device__ float g_sumexp[(size_t)NROWS * Mv];
__device__ float g_logp[Mv];
__device__ int g_fb;   // 1 -> tcgen05 unavailable, mma.sync fallback must run

// ---------------- generic helpers ----------------
__device__ __forceinline__ uint32_t smem_u32(const void* p) {
    return (uint32_t)__cvta_generic_to_shared(p);
}
__device__ __forceinline__ uint16_t cvt_e4m3x2(float lo, float hi) {
    uint16_t r;
    asm("cvt.rn.satfinite.e4m3x2.f32 %0, %1, %2;" : "=h"(r) : "f"(hi), "f"(lo));
    return r;
}

// warp-cooperative target dot: g_tgt[t] = x[t].W[safe_tgt], g_xdw[t] = x[t].wsum
__device__ __forceinline__ void target_one(const float* __restrict__ x,
                                           const float* __restrict__ W,
                                           const int* __restrict__ tg,
                                           int t, int lane) {
    int tv = tg[t];
    int safe = tv < 0 ? 0 : (tv >= Vv ? Vv - 1 : tv);
    const float4* xr = reinterpret_cast<const float4*>(x + (size_t)t * Hv);
    const float4* wr = reinterpret_cast<const float4*>(W + (size_t)safe * Hv);
    const float4* sr = reinterpret_cast<const float4*>(g_wsum);
    float d1 = 0.f, d2 = 0.f;
#pragma unroll 4
    for (int i = lane; i < Hv / 4; i += 32) {
        float4 a = xr[i], b = wr[i], c = sr[i];
        d1 += a.x * b.x + a.y * b.y + a.z * b.z + a.w * b.w;
        d2 += a.x * c.x + a.y * c.y + a.z * c.z + a.w * c.w;
    }
#pragma unroll
    for (int o = 16; o; o >>= 1) {
        d1 += __shfl_xor_sync(0xFFFFFFFFu, d1, o);
        d2 += __shfl_xor_sync(0xFFFFFFFFu, d2, o);
    }
    if (lane == 0) { g_tgt[t] = d1; g_xdw[t] = d2; }
}

// fallback loader: 4 fp8 at (row, k) [k%4==0] -> 4 bf16 (scaled)
__device__ __forceinline__ uint2 ld_blk8(const unsigned char* base, int row, int k, float scale) {
    size_t tile = ((size_t)(row >> 7) * 32 + (k >> 7)) * 16384;
    int rr = row & 127, cc = k & 127;
    int chunk = rr * 128 + (cc >> 4) * 16;
    int sw = chunk ^ ((chunk >> 3) & 0x70);
    uint32_t v = *reinterpret_cast<const uint32_t*>(base + tile + (size_t)sw + (cc & 15));
    __nv_bfloat16 b[4];
#pragma unroll
    for (int i = 0; i < 4; i++) {
        __nv_fp8_storage_t fs = (__nv_fp8_storage_t)((v >> (8 * i)) & 0xFF);
        __half_raw hr = __nv_cvt_fp8_to_halfraw(fs, __NV_E4M3);
        float f = __half2float(*reinterpret_cast<__half*>(&hr)) * scale;
        b[i] = __float2bfloat16(f);
    }
    uint2 r;
    r.x = *reinterpret_cast<uint32_t*>(&b[0]);
    r.y = *reinterpret_cast<uint32_t*>(&b[2]);
    return r;
}

// ---------------- W pass: fp32 -> blocked swizzled e4m3 (x64) + col partial sums ----
__global__ void __launch_bounds__(256) wpass3_kernel(const float* __restrict__ W) {
    __shared__ float cs[256][17];   // padded: conflict-free column-sum reduction
    const int tid = threadIdx.x;
    const int kb = blockIdx.x;      // 0..31 (128 K each)
    const int vb = blockIdx.y;      // 0..249 (128 rows each)
    const float* src = W + (size_t)vb * 128 * Hv + kb * 128;
    unsigned char* dst = g_W8 + ((size_t)(vb * 32 + kb)) * 16384;
    const int c16 = tid & 7;
    float s[16];
#pragma unroll
    for (int k = 0; k < 16; k++) s[k] = 0.f;
#pragma unroll
    for (int j = 0; j < 4; j++) {
        int r = (tid >> 3) + j * 32;
        const float4* p = reinterpret_cast<const float4*>(src + (size_t)r * Hv + c16 * 16);
        float v[16];
#pragma unroll
        for (int q = 0; q < 4; q++) {
            float4 f = p[q];
            v[q * 4 + 0] = f.x; v[q * 4 + 1] = f.y; v[q * 4 + 2] = f.z; v[q * 4 + 3] = f.w;
        }
#pragma unroll
        for (int k = 0; k < 16; k++) s[k] += v[k];
        uint16_t h[8];
#pragma unroll
        for (int q = 0; q < 8; q++)
            h[q] = cvt_e4m3x2(v[2 * q] * WSCALE, v[2 * q + 1] * WSCALE);
        uint4 u;
        u.x = (uint32_t)h[0] | ((uint32_t)h[1] << 16);
        u.y = (uint32_t)h[2] | ((uint32_t)h[3] << 16);
        u.z = (uint32_t)h[4] | ((uint32_t)h[5] << 16);
        u.w = (uint32_t)h[6] | ((uint32_t)h[7] << 16);
        int boff = r * 128 + c16 * 16;
        int sw = boff ^ ((boff >> 3) & 0x70);
        *reinterpret_cast<uint4*>(dst + sw) = u;
    }
#pragma unroll
    for (int k = 0; k < 16; k++) cs[tid][k] = s[k];
    __syncthreads();
    for (int step = 128; step >= 8; step >>= 1) {
        if (tid < step) {
#pragma unroll
            for (int k = 0; k < 16; k++) cs[tid][k] += cs[tid + step][k];
        }
        __syncthreads();
    }
    if (tid < 8) {
#pragma unroll
        for (int k = 0; k < 16; k++)
            g_wsumP[(size_t)vb * Hv + kb * 128 + tid * 16 + k] = cs[tid][k];
    }
}

// ---------------- x pass: fp32 -> blocked swizzled e4m3 ----------------
__global__ void __launch_bounds__(256) convx3_kernel(const float* __restrict__ X) {
    const int tid = threadIdx.x;
    const int kb = blockIdx.x;      // 0..31
    const int mb = blockIdx.y;      // 0..31
    const float* src = X + (size_t)mb * 128 * Hv + kb * 128;
    unsigned char* dst = g_X8 + ((size_t)(mb * 32 + kb)) * 16384;
    const int c16 = tid & 7;
#pragma unroll
    for (int j = 0; j < 4; j++) {
        int r = (tid >> 3) + j * 32;
        const float4* p = reinterpret_cast<const float4*>(src + (size_t)r * Hv + c16 * 16);
        float v[16];
#pragma unroll
        for (int q = 0; q < 4; q++) {
            float4 f = p[q];
            v[q * 4 + 0] = f.x; v[q * 4 + 1] = f.y; v[q * 4 + 2] = f.z; v[q * 4 + 3] = f.w;
        }
        uint16_t h[8];
#pragma unroll
        for (int q = 0; q < 8; q++)
            h[q] = cvt_e4m3x2(v[2 * q], v[2 * q + 1]);
        uint4 u;
        u.x = (uint32_t)h[0] | ((uint32_t)h[1] << 16);
        u.y = (uint32_t)h[2] | ((uint32_t)h[3] << 16);
        u.z = (uint32_t)h[4] | ((uint32_t)h[5] << 16);
        u.w = (uint32_t)h[6] | ((uint32_t)h[7] << 16);
        int boff = r * 128 + c16 * 16;
        int sw = boff ^ ((boff >> 3) & 0x70);
        *reinterpret_cast<uint4*>(dst + sw) = u;
    }
}

__global__ void wsum_reduce_kernel() {
    int h = blockIdx.x * blockDim.x + threadIdx.x;
    float s = 0.f;
    for (int seg = 0; seg < 250; seg++) s += g_wsumP[(size_t)seg * Hv + h];
    g_wsum[h] = s;
}

// ---------------- fallback-only target kernel (tcgen05 path does this in-GEMM) ----
__global__ void target_fb_kernel(const float* __restrict__ x, const float* __restrict__ W,
                                 const int* __restrict__ tg) {
    if (*(volatile int*)&g_fb == 0) return;
    int warp = threadIdx.x >> 5, lane = threadIdx.x & 31;
    int t = blockIdx.x * 8 + warp;
    if (t < Mv) target_one(x, W, tg, t, lane);
}

// ---------------- reset: flag + W pad tiles only ----------------
__global__ void reset_kernel() {
    long tid0 = (long)blockIdx.x * blockDim.x + threadIdx.x;
    uint4* pad = reinterpret_cast<uint4*>(g_W8 + (size_t)250 * 32 * 16384);
    if (tid0 < (long)(2 * 32 * 16384 / 16)) pad[tid0] = make_uint4(0, 0, 0, 0);
    if (tid0 == 0) g_fb = 0;
}

// ============================================================================
// tcgen05 FP8 persistent path (arch-specific variant only) — round-12 proven
// pipeline; NEW: epilogue warps compute target dots in pre-loop slack
// (no consumer inside the kernel -> no gating, pure slack fill).
// ============================================================================
#define NSTAGE 4
#define STAGE_BYTES 32768         // A 16K + B 16K
#define SMEM_HDR 4096             // barriers [8,104) + epi_part [256,2304); DATA at 4096
#define GEMM_SMEM (SMEM_HDR + NSTAGE * STAGE_BYTES)
#define GTHREADS 320              // warps 0-7 epilogue, 8 producer, 9 mma/relay

#if HAS_TCGEN05
__device__ __forceinline__ uint32_t elect_one() {
    uint32_t pred;
    asm volatile("{\n\t.reg .pred p;\n\telect.sync _|p, 0xFFFFFFFF;\n\tselp.b32 %0, 1, 0, p;\n\t}"
                 : "=r"(pred));
    return pred;
}
__device__ __forceinline__ void mbar_init(uint32_t a, uint32_t cnt) {
    asm volatile("mbarrier.init.shared.b64 [%0], %1;" :: "r"(a), "r"(cnt) : "memory");
}
__device__ __forceinline__ void mbar_expect_tx(uint32_t a, uint32_t tx) {
    asm volatile("mbarrier.arrive.expect_tx.shared.b64 _, [%0], %1;" :: "r"(a), "r"(tx) : "memory");
}
__device__ __forceinline__ void mbar_arrive(uint32_t a) {
    asm volatile("mbarrier.arrive.shared.b64 _, [%0];" :: "r"(a) : "memory");
}
__device__ __forceinline__ void mbar_arrive_rank(uint32_t a, uint32_t rank) {
    asm volatile("{\n\t.reg .b32 ra;\n\tmapa.shared::cluster.u32 ra, %0, %1;\n\t"
                 "mbarrier.arrive.shared::cluster.b64 _, [ra];\n\t}" :: "r"(a), "r"(rank) : "memory");
}
__device__ __forceinline__ void mbar_wait(uint32_t a, uint32_t parity) {
    asm volatile(
        "{\n\t.reg .pred P;\n"
        "WL%=:\n\t"
        "mbarrier.try_wait.parity.acquire.cta.shared::cta.b64 P, [%0], %1, 0x989680;\n\t"
        "@P bra WD%=;\n\t"
        "bra WL%=;\n"
        "WD%=:\n\t}"
        :: "r"(a), "r"(parity) : "memory");
}
__device__ __forceinline__ void bulk_g2s(uint32_t dst, const void* src, uint32_t bytes,
                                         uint32_t mbar) {
    asm volatile(
        "cp.async.bulk.shared::cluster.global.mbarrier::complete_tx::bytes [%0], [%1], %2, [%3];"
        :: "r"(dst), "l"(src), "r"(bytes), "r"(mbar) : "memory");
}
__device__ __forceinline__ void bulk_g2s_mc(uint32_t dst, const void* src, uint32_t bytes,
                                            uint32_t mbar, uint16_t mask) {
    asm volatile(
        "cp.async.bulk.shared::cluster.global.mbarrier::complete_tx::bytes.multicast::cluster "
        "[%0], [%1], %2, [%3], %4;"
        :: "r"(dst), "l"(src), "r"(bytes), "r"(mbar), "h"(mask) : "memory");
}
__device__ __forceinline__ void cluster_sync_() {
    asm volatile("barrier.cluster.arrive.aligned;" ::: "memory");
    asm volatile("barrier.cluster.wait.aligned;" ::: "memory");
}
__device__ __forceinline__ void tc_fence_after() {
    asm volatile("tcgen05.fence::after_thread_sync;" ::: "memory");
}
__device__ __forceinline__ void tc_fence_before() {
    asm volatile("tcgen05.fence::before_thread_sync;" ::: "memory");
}
__device__ __forceinline__ void tc_wait_ld() {
    asm volatile("tcgen05.wait::ld.sync.aligned;" ::: "memory");
}
__device__ __forceinline__ void tmem_alloc_cg2(uint32_t smem_addr, uint32_t ncols) {
    asm volatile("tcgen05.alloc.cta_group::2.sync.aligned.shared::cta.b32 [%0], %1;"
                 :: "r"(smem_addr), "r"(ncols) : "memory");
}
__device__ __forceinline__ void tmem_dealloc_cg2(uint32_t tmem, uint32_t ncols) {
    asm volatile("tcgen05.relinquish_alloc_permit.cta_group::2.sync.aligned;");
    asm volatile("tcgen05.dealloc.cta_group::2.sync.aligned.b32 %0, %1;" :: "r"(tmem), "r"(ncols));
}
__device__ __forceinline__ void mma_f8_ss_cg2(uint32_t d_tmem, uint64_t a_desc, uint64_t b_desc,
                                              uint32_t idesc, uint32_t en) {
    asm volatile(
        "{\n\t.reg .pred p;\n\t"
        "setp.ne.u32 p, %6, 0;\n\t"
        "tcgen05.mma.cta_group::2.kind::f8f6f4 [%0], %1, %2, %3, "
        "{%4, %4, %4, %4, %4, %4, %4, %4}, p;\n\t}"
        :: "r"(d_tmem), "l"(a_desc), "l"(b_desc), "r"(idesc),
           "r"(0u), "r"(0u), "r"(en)
        : "memory");
}
__device__ __forceinline__ void commit_mc_cg2(uint32_t mbar, uint16_t mask) {
    asm volatile(
        "tcgen05.commit.cta_group::2.mbarrier::arrive::one.shared::cluster.multicast::cluster.b64 [%0], %1;"
        :: "r"(mbar), "h"(mask) : "memory");
}
__device__ __forceinline__ void ldtm_x32(uint32_t* r, uint32_t addr) {
    asm volatile(
        "tcgen05.ld.sync.aligned.32x32b.x32.b32 "
        "{%0, %1, %2, %3, %4, %5, %6, %7, "
        " %8, %9, %10, %11, %12, %13, %14, %15, "
        " %16, %17, %18, %19, %20, %21, %22, %23, "
        " %24, %25, %26, %27, %28, %29, %30, %31}, [%32];"
        : "=r"(r[0]), "=r"(r[1]), "=r"(r[2]), "=r"(r[3]),
          "=r"(r[4]), "=r"(r[5]), "=r"(r[6]), "=r"(r[7]),
          "=r"(r[8]), "=r"(r[9]), "=r"(r[10]), "=r"(r[11]),
          "=r"(r[12]), "=r"(r[13]), "=r"(r[14]), "=r"(r[15]),
          "=r"(r[16]), "=r"(r[17]), "=r"(r[18]), "=r"(r[19]),
          "=r"(r[20]), "=r"(r[21]), "=r"(r[22]), "=r"(r[23]),
          "=r"(r[24]), "=r"(r[25]), "=r"(r[26]), "=r"(r[27]),
          "=r"(r[28]), "=r"(r[29]), "=r"(r[30]), "=r"(r[31])
        : "r"(addr));
}
__device__ __forceinline__ uint64_t make_desc(uint32_t addr) {
    const uint64_t base = (uint64_t(2) << 61) | (uint64_t(1) << 46) |
                          (uint64_t(64) << 32) | (uint64_t(1) << 16);
    return base | ((uint64_t)(addr >> 4) & 0x3FFF);
}
#endif // HAS_TCGEN05

// Persistent cluster (4,1,1) x 33 (132 CTAs). Per cluster tile: M=512 x N=256.
// Pair p covers M rows [p*256, p*256+256) via one cg2 M=256 MMA per K-step.
// TMEM ping-pong: D buffers at cols 0 and 256; epilogue of tile t overlaps
// MMA of tile t+1. EMPTY committed 0xF by both pair leaders (count=2).
// Epilogue warps compute the exact-fp32 target dots in their pre-loop slack.
__global__ void __launch_bounds__(GTHREADS, 1) __cluster_dims__(4, 1, 1)
gemm_kernel(const float* __restrict__ x, const float* __restrict__ Wp,
            const int* __restrict__ tg) {
#if HAS_TCGEN05
    extern __shared__ char smem[];
    const uint32_t sb = smem_u32(smem);
    float* epi_part = reinterpret_cast<float*>(smem + 256);   // [2][8][32] = 2048B
    const int tid = threadIdx.x;
    const int wid = tid >> 5, lane = tid & 31;
    const int r = blockIdx.x & 3;          // cluster rank
    const int cid = blockIdx.x >> 2;       // cluster id 0..32
    const int p = r >> 1, prank = r & 1;   // pair, rank within pair

    const uint32_t FULL = sb + 8;          // 4 x 8B
    const uint32_t EMPTY = sb + 40;        // 4 x 8B
    const uint32_t TFULL = sb + 72;        // 2 x 8B (MMA done, per TMEM buffer)
    const uint32_t TEPI = sb + 88;         // 2 x 8B (epilogue done, on pair leader)
    const uint32_t DATA = sb + SMEM_HDR;

    const int lo = (cid * TOT_TILES) / NCLUSTERS;
    const int hi = ((cid + 1) * TOT_TILES) / NCLUSTERS;
    const int ntl = hi - lo;

    if (wid == 9) tmem_alloc_cg2(sb, 512);
    if (tid == 0) {
#pragma unroll
        for (int s = 0; s < NSTAGE; s++) {
            mbar_init(FULL + 8 * s, prank ? 1u : 2u);
            mbar_init(EMPTY + 8 * s, 2u);   // commits from BOTH pair leaders
        }
        mbar_init(TFULL + 0, 1u);
        mbar_init(TFULL + 8, 1u);
        mbar_init(TEPI + 0, 2u);
        mbar_init(TEPI + 8, 2u);
    }
    __syncthreads();
    uint32_t tmem;
    asm volatile("ld.shared.b32 %0, [%1];" : "=r"(tmem) : "r"(sb));
    cluster_sync_();

    const uint16_t pair_mask = (p == 0) ? 0x3 : 0xC;

    if (wid == 8) {
        // ---- producer: elected thread streams A + (rank<2) multicast B ----
        if (elect_one()) {
            const uint16_t bmask = prank ? 0xA : 0x5;   // {1,3} : {0,2}
            int git = 0;
            for (int lt = 0; lt < ntl; ++lt) {
                const int t = lo + lt;
                const int tm = t & 7, nt = t >> 3;
                const int rbA = tm * 4 + r;            // A row-tile for this CTA
                const int rbB = nt * 2 + prank;        // B row-tile (ranks 0,1 load)
                for (int it = 0; it < 32; ++it, ++git) {
                    const int slot = git & (NSTAGE - 1);
                    const int u = git >> 2;
                    if (git >= NSTAGE) mbar_wait(EMPTY + 8 * slot, (u + 1) & 1);
                    const uint32_t fb = FULL + 8 * slot;
                    mbar_expect_tx(fb, STAGE_BYTES);
                    const uint32_t d = DATA + slot * STAGE_BYTES;
                    bulk_g2s(d, g_X8 + ((size_t)(rbA * 32 + it)) * 16384, 16384, fb);
                    if (r < 2)
                        bulk_g2s_mc(d + 16384, g_W8 + ((size_t)(rbB * 32 + it)) * 16384,
                                    16384, fb, bmask);
                }
            }
        }
    } else if (wid == 9) {
        if (prank == 1) {
            // ---- relay: forward local stage readiness to pair leader ----
            if (lane == 0) {
                int git = 0;
                for (int lt = 0; lt < ntl; ++lt)
                    for (int it = 0; it < 32; ++it, ++git) {
                        const int slot = git & (NSTAGE - 1);
                        mbar_wait(FULL + 8 * slot, (git >> 2) & 1);
                        mbar_arrive_rank(FULL + 8 * slot, (uint32_t)(r - 1));
                    }
            }
        } else {
            // ---- MMA issuer on pair leaders ----
            const uint32_t IDESC = (1u << 4) | ((256u / 8) << 17) | ((256u / 16) << 24);
            tc_fence_after();
            int git = 0;
            for (int lt = 0; lt < ntl; ++lt) {
                const int dbuf = lt & 1;
                if (lt >= 2) mbar_wait(TEPI + 8 * dbuf, ((lt >> 1) - 1) & 1);
                const uint32_t dt = tmem + dbuf * 256;
                for (int it = 0; it < 32; ++it, ++git) {
                    const int slot = git & (NSTAGE - 1);
                    mbar_wait(FULL + 8 * slot, (git >> 2) & 1);
                    if (elect_one()) {
                        const uint32_t base = DATA + slot * STAGE_BYTES;
                        uint64_t a = make_desc(base);
                        uint64_t b = make_desc(base + 16384);
#pragma unroll
                        for (int k = 0; k < 4; ++k) {
                            uint32_t en = (it | k) ? 1u : 0u;
                            mma_f8_ss_cg2(dt, a + k * 2, b + k * 2, IDESC, en);
                        }
                        commit_mc_cg2(EMPTY + 8 * slot, 0xF);   // couple both pairs
                    }
                }
                if (elect_one()) commit_mc_cg2(TFULL + 8 * dbuf, pair_mask);
            }
        }
    } else {
        // ---- epilogue warps 0-7: target dots in pre-loop slack, then tiles ----
        {
            const int gw = (blockIdx.x << 3) + wid;    // 0..1055
            for (int t = gw; t < Mv; t += 8 * 4 * NCLUSTERS)
                target_one(x, Wp, tg, t, lane);
        }
        const int cgrp = wid >> 2;          // col group: 0 -> [0,128), 1 -> [128,256)
        const int rowloc = (wid & 3) * 32 + lane;
        for (int lt = 0; lt < ntl; ++lt) {
            const int t = lo + lt;
            const int tm = t & 7, nt = t >> 3;
            const int dbuf = lt & 1;
            mbar_wait(TFULL + 8 * dbuf, (lt >> 1) & 1);
            tc_fence_after();
            const uint32_t dbase = tmem + dbuf * 256 + cgrp * 128;
            float s = 0.f;
#pragma unroll
            for (int c2 = 0; c2 < 2; ++c2) {
                uint32_t rg[2][32];
                ldtm_x32(rg[0], dbase + (c2 * 2) * 32);
                ldtm_x32(rg[1], dbase + (c2 * 2 + 1) * 32);
                tc_wait_ld();
#pragma unroll
                for (int i = 0; i < 32; ++i)
                    s += __expf(__uint_as_float(rg[0][i]) * WISCALE) +
                         __expf(__uint_as_float(rg[1][i]) * WISCALE);
            }
            tc_fence_before();
            epi_part[(dbuf * 8 + wid) * 32 + lane] = s;
            asm volatile("bar.sync 1, 256;" ::: "memory");
            if (wid < 4) {
                const int token = tm * 512 + p * 256 + prank * 128 + rowloc;
                float tot = s + epi_part[(dbuf * 8 + wid + 4) * 32 + lane];
                g_sumexp[(size_t)nt * Mv + token] = tot;
            }
            if (tid == 0) {
                if (prank == 0) mbar_arrive(TEPI + 8 * dbuf);
                else            mbar_arrive_rank(TEPI + 8 * dbuf, (uint32_t)(r - 1));
            }
        }
    }

    __syncthreads();
    if (wid == 9) tmem_dealloc_cg2(tmem, 512);
    cluster_sync_();
#else
    (void)x; (void)Wp; (void)tg;
    if (threadIdx.x == 0 && blockIdx.x == 0) g_fb = 1;
#endif
}

// ============================================================================
// Fallback mma.sync GEMM (runs only if g_fb == 1); converts fp8 -> bf16 on load.
// ============================================================================
#define ASTRIDE 40

__global__ void __launch_bounds__(256) gemm_fb_kernel() {
    if (*(volatile int*)&g_fb == 0) return;
    __shared__ __nv_bfloat16 As[128 * ASTRIDE];
    __shared__ __nv_bfloat16 Bs[128 * ASTRIDE];
    __shared__ float rsum[2][128];

    const int tid = threadIdx.x;
    const int m0 = blockIdx.x * 128;
    const int n0 = blockIdx.y * 128;
    const int warp = tid >> 5, lane = tid & 31;
    const int mw = warp >> 1, nw = warp & 1;

    float acc[2][8][4];
#pragma unroll
    for (int a = 0; a < 2; a++)
#pragma unroll
        for (int b = 0; b < 8; b++)
#pragma unroll
            for (int c = 0; c < 4; c++) acc[a][b][c] = 0.f;

    uint2 pa[4], pb[4];
    auto loadG = [&](int kk) {
#pragma unroll
        for (int j = 0; j < 4; j++) {
            int i = tid + j * 256;
            int row = i >> 3, seg = i & 7;
            pa[j] = ld_blk8(g_X8, m0 + row, kk + seg * 4, 1.0f);
            pb[j] = ld_blk8(g_W8, n0 + row, kk + seg * 4, WISCALE);
        }
    };
    auto storeS = [&]() {
#pragma unroll
        for (int j = 0; j < 4; j++) {
            int i = tid + j * 256;
            int row = i >> 3, seg = i & 7;
            *reinterpret_cast<uint2*>(As + row * ASTRIDE + seg * 4) = pa[j];
            *reinterpret_cast<uint2*>(Bs + row * ASTRIDE + seg * 4) = pb[j];
        }
    };

    loadG(0);
    storeS();

    for (int it = 0; it < 128; ++it) {
        __syncthreads();
        if (it + 1 < 128) loadG((it + 1) * 32);

#pragma unroll
        for (int ks = 0; ks < 32; ks += 16) {
            uint32_t a[2][4];
#pragma unroll
            for (int mt = 0; mt < 2; mt++) {
                int row = mw * 32 + mt * 16 + (lane & 15);
                int col = ks + ((lane >> 4) << 3);
                uint32_t addr = smem_u32(As + row * ASTRIDE + col);
                asm volatile(
                    "ldmatrix.sync.aligned.m8n8.x4.shared.b16 {%0,%1,%2,%3}, [%4];"
                    : "=r"(a[mt][0]), "=r"(a[mt][1]), "=r"(a[mt][2]), "=r"(a[mt][3])
                    : "r"(addr));
            }
            uint32_t b[8][2];
#pragma unroll
            for (int np = 0; np < 4; np++) {
                int n = nw * 64 + np * 16 + (lane & 7) + ((lane >> 4) << 3);
                int kq = ks + (((lane >> 3) & 1) << 3);
                uint32_t addr = smem_u32(Bs + n * ASTRIDE + kq);
                asm volatile(
                    "ldmatrix.sync.aligned.m8n8.x4.shared.b16 {%0,%1,%2,%3}, [%4];"
                    : "=r"(b[2 * np][0]), "=r"(b[2 * np][1]),
                      "=r"(b[2 * np + 1][0]), "=r"(b[2 * np + 1][1])
                    : "r"(addr));
            }
#pragma unroll
            for (int mt = 0; mt < 2; mt++)
#pragma unroll
                for (int nt = 0; nt < 8; nt++) {
                    float* c = acc[mt][nt];
                    asm volatile(
                        "mma.sync.aligned.m16n8k16.row.col.f32.bf16.bf16.f32 "
                        "{%0,%1,%2,%3}, {%4,%5,%6,%7}, {%8,%9}, {%0,%1,%2,%3};"
                        : "+f"(c[0]), "+f"(c[1]), "+f"(c[2]), "+f"(c[3])
                        : "r"(a[mt][0]), "r"(a[mt][1]), "r"(a[mt][2]), "r"(a[mt][3]),
                          "r"(b[nt][0]), "r"(b[nt][1]));
                }
        }
        __syncthreads();
        if (it + 1 < 128) storeS();
    }

#pragma unroll
    for (int mt = 0; mt < 2; mt++) {
        float slo = 0.f, shi = 0.f;
#pragma unroll
        for (int nt = 0; nt < 8; nt++) {
            slo += __expf(acc[mt][nt][0]) + __expf(acc[mt][nt][1]);
            shi += __expf(acc[mt][nt][2]) + __expf(acc[mt][nt][3]);
        }
        slo += __shfl_xor_sync(0xFFFFFFFFu, slo, 1);
        slo += __shfl_xor_sync(0xFFFFFFFFu, slo, 2);
        shi += __shfl_xor_sync(0xFFFFFFFFu, shi, 1);
        shi += __shfl_xor_sync(0xFFFFFFFFu, shi, 2);
        if ((lane & 3) == 0) {
            int rr = mw * 32 + mt * 16 + (lane >> 2);
            rsum[nw][rr] = slo;
            rsum[nw][rr + 8] = shi;
        }
    }
    __syncthreads();
    if (tid < 128) {
        g_sumexp[(size_t)blockIdx.y * Mv + m0 + tid] = rsum[0][tid] + rsum[1][tid];
    }
}

// ---------------- per-token logp ----------------
__global__ void token_reduce_kernel(const int* __restrict__ tg) {
    int t = blockIdx.x * blockDim.x + threadIdx.x;
    if (t >= Mv) return;
    const int fb = g_fb;
    const int rows = fb ? NROWS : NTILE_TC;   // read exactly what was written
    float s = 0.f;
    for (int c = 0; c < rows; c++) s += g_sumexp[(size_t)c * Mv + t];
    if (fb == 0) s -= 256.0f;   // tcgen05 path: 256 zero-logit pad columns
    g_logp[t] = (tg[t] != IGNORE_INDEX) ? (g_tgt[t] - logf(s)) : 0.f;
}

// ---------------- final loss / outputs ----------------
__global__ void final_kernel(const int* __restrict__ tg, float* __restrict__ out) {
    __shared__ float red[256];
    __shared__ int redi[256];
    __shared__ float seq[8];
    __shared__ float xw[2];
    int tid = threadIdx.x;

    for (int s = 0; s < 8; s++) {
        float v = 0.f; int c = 0;
        for (int i = tid; i < Sv; i += 256) {
            int t = s * Sv + i;
            v += g_logp[t];
            c += (tg[t] != IGNORE_INDEX);
        }
        red[tid] = v; redi[tid] = c;
        __syncthreads();
        for (int o = 128; o; o >>= 1) {
            if (tid < o) { red[tid] += red[tid + o]; redi[tid] += redi[tid + o]; }
            __syncthreads();
        }
        if (tid == 0) seq[s] = red[0] / (float)redi[0];
        __syncthreads();
    }

    for (int h = 0; h < 2; h++) {
        float v = 0.f;
        for (int i = tid; i < 4 * Sv; i += 256) v += g_xdw[h * 4 * Sv + i];
        red[tid] = v;
        __syncthreads();
        for (int o = 128; o; o >>= 1) {
            if (tid < o) red[tid] += red[tid + o];
            __syncthreads();
        }
        if (tid == 0) xw[h] = red[0];
        __syncthreads();
    }

    if (tid == 0) {
        float loss = 0.f;
#pragma unroll
        for (int i = 0; i < 4; i++) {
            float z = 0.1f * (seq[i] - seq[4 + i]);
            float ls = fminf(z, 0.f) - log1pf(expf(-fabsf(z)));   // log_sigmoid(z)
            loss += -ls;
        }
        loss *= 0.25f;
        out[0] = loss;
#pragma unroll
        for (int i = 0; i < 8; i++) out[1 + i] = seq[i];
        const float denom = 4.0f * (float)Sv * (float)Vv;
        out[9] = xw[0] / denom;
        out[10] = xw[1] / denom;
        out[11] = 0.0f;
    }
}

// ---------------- launch ----------------
extern "C" void kernel_launch(void* const* d_in, const int* in_sizes, int n_in,
                              void* d_out, int out_size) {
    const float* x = nullptr;
    const float* W = nullptr;
    const int* tg = nullptr;
    for (int i = 0; i < n_in; i++) {
        if (in_sizes[i] == Vv * Hv) W = (const float*)d_in[i];
        else if (in_sizes[i] == Mv * Hv) x = (const float*)d_in[i];
        else if (in_sizes[i] == Mv) tg = (const int*)d_in[i];
    }
    float* out = (float*)d_out;

    cudaFuncSetAttribute(gemm_kernel, cudaFuncAttributeMaxDynamicSharedMemorySize, GEMM_SMEM);

    wpass3_kernel<<<dim3(32, 250), 256>>>(W);                 // 1
    convx3_kernel<<<dim3(32, 32), 256>>>(x);                  // 2
    wsum_reduce_kernel<<<16, 256>>>();                        // 3 (g_wsum before gemm)
    reset_kernel<<<256, 256>>>();                             // 4
    gemm_kernel<<<4 * NCLUSTERS, GTHREADS, GEMM_SMEM>>>(x, W, tg); // 5 (+in-GEMM target)
    target_fb_kernel<<<512, 256>>>(x, W, tg);                 // 6 (no-op if tcgen05 ran)
    gemm_fb_kernel<<<dim3(32, 250), 256>>>();                 // 7 (no-op if tcgen05 ran)
    token_reduce_kernel<<<32, 128>>>(tg);                     // 8
    final_kernel<<<1, 256>>>(tg, out);                        // 9
}

// round 15
// speedup vs baseline: 1.1656x; 1.0062x over previous
#include <cuda_runtime.h>
#include <cuda_bf16.h>
#include <cuda_fp8.h>
#include <cstdint>

// Problem constants
#define Hv 4096
#define Vv 32000
#define Mv 4096          // B*S tokens
#define Sv 512
#define NROWS 250        // fallback sum-exp rows; tcgen05 path uses 126
#define NTILE_TC 126     // V padded to 32256 = 126 * 256
#define IGNORE_INDEX (-100)
#define WSCALE 64.0f
#define WISCALE 0.015625f
#define NCLUSTERS 33     // 132 CTAs — proven single-wave packing
#define TOT_TILES (8 * NTILE_TC)   // 1008: tm fastest (8 of M=512), nt = t>>3

#if defined(__CUDA_ARCH_FEAT_SM103_ALL) || defined(__CUDA_ARCH_FEAT_SM100_ALL) || \
    (defined(__CUDA_ARCH_FAMILY_SPECIFIC__) && (__CUDA_ARCH_FAMILY_SPECIFIC__ >= 1000))
#define HAS_TCGEN05 1
#else
#define HAS_TCGEN05 0
#endif

// ---------------- device scratch ----------------
__device__ __align__(128) unsigned char g_W8[(size_t)252 * 32 * 16384];  // 132 MB (2 pad row-tiles)
__device__ __align__(128) unsigned char g_X8[(size_t)32 * 32 * 16384];   // 16 MB
__device__ float g_wsumP[(size_t)250 * Hv];
__device__ float g_wsum[Hv];
__device__ float g_tgt[Mv];
__device__ float g_xdw[Mv];
__device__ float g_sumexp[(size_t)NROWS * Mv];
__device__ float g_logp[Mv];
__device__ int g_fb;   // 1 -> tcgen05 unavailable, mma.sync fallback must run

// ---------------- generic helpers ----------------
__device__ __forceinline__ uint32_t smem_u32(const void* p) {
    return (uint32_t)__cvta_generic_to_shared(p);
}
__device__ __forceinline__ uint16_t cvt_e4m3x2(float lo, float hi) {
    uint16_t r;
    asm("cvt.rn.satfinite.e4m3x2.f32 %0, %1, %2;" : "=h"(r) : "f"(hi), "f"(lo));
    return r;
}

// warp-cooperative target dot: g_tgt[t] = x[t].W[safe_tgt], g_xdw[t] = x[t].wsum
__device__ __forceinline__ void target_one(const float* __restrict__ x,
                                           const float* __restrict__ W,
                                           const int* __restrict__ tg,
                                           int t, int lane) {
    int tv = tg[t];
    int safe = tv < 0 ? 0 : (tv >= Vv ? Vv - 1 : tv);
    const float4* xr = reinterpret_cast<const float4*>(x + (size_t)t * Hv);
    const float4* wr = reinterpret_cast<const float4*>(W + (size_t)safe * Hv);
    const float4* sr = reinterpret_cast<const float4*>(g_wsum);
    float d1 = 0.f, d2 = 0.f;
#pragma unroll 4
    for (int i = lane; i < Hv / 4; i += 32) {
        float4 a = xr[i], b = wr[i], c = sr[i];
        d1 += a.x * b.x + a.y * b.y + a.z * b.z + a.w * b.w;
        d2 += a.x * c.x + a.y * c.y + a.z * c.z + a.w * c.w;
    }
#pragma unroll
    for (int o = 16; o; o >>= 1) {
        d1 += __shfl_xor_sync(0xFFFFFFFFu, d1, o);
        d2 += __shfl_xor_sync(0xFFFFFFFFu, d2, o);
    }
    if (lane == 0) { g_tgt[t] = d1; g_xdw[t] = d2; }
}

// fallback loader: 4 fp8 at (row, k) [k%4==0] -> 4 bf16 (scaled)
__device__ __forceinline__ uint2 ld_blk8(const unsigned char* base, int row, int k, float scale) {
    size_t tile = ((size_t)(row >> 7) * 32 + (k >> 7)) * 16384;
    int rr = row & 127, cc = k & 127;
    int chunk = rr * 128 + (cc >> 4) * 16;
    int sw = chunk ^ ((chunk >> 3) & 0x70);
    uint32_t v = *reinterpret_cast<const uint32_t*>(base + tile + (size_t)sw + (cc & 15));
    __nv_bfloat16 b[4];
#pragma unroll
    for (int i = 0; i < 4; i++) {
        __nv_fp8_storage_t fs = (__nv_fp8_storage_t)((v >> (8 * i)) & 0xFF);
        __half_raw hr = __nv_cvt_fp8_to_halfraw(fs, __NV_E4M3);
        float f = __half2float(*reinterpret_cast<__half*>(&hr)) * scale;
        b[i] = __float2bfloat16(f);
    }
    uint2 r;
    r.x = *reinterpret_cast<uint32_t*>(&b[0]);
    r.y = *reinterpret_cast<uint32_t*>(&b[2]);
    return r;
}

// ---------------- W pass: fp32 -> blocked swizzled e4m3 (x64) + col partial sums ----
__global__ void __launch_bounds__(256) wpass3_kernel(const float* __restrict__ W) {
    __shared__ float cs[256][17];   // padded: conflict-free column-sum reduction
    const int tid = threadIdx.x;
    const int kb = blockIdx.x;      // 0..31 (128 K each)
    const int vb = blockIdx.y;      // 0..249 (128 rows each)
    const float* src = W + (size_t)vb * 128 * Hv + kb * 128;
    unsigned char* dst = g_W8 + ((size_t)(vb * 32 + kb)) * 16384;
    const int c16 = tid & 7;
    float s[16];
#pragma unroll
    for (int k = 0; k < 16; k++) s[k] = 0.f;
#pragma unroll
    for (int j = 0; j < 4; j++) {
        int r = (tid >> 3) + j * 32;
        const float4* p = reinterpret_cast<const float4*>(src + (size_t)r * Hv + c16 * 16);
        float v[16];
#pragma unroll
        for (int q = 0; q < 4; q++) {
            float4 f = p[q];
            v[q * 4 + 0] = f.x; v[q * 4 + 1] = f.y; v[q * 4 + 2] = f.z; v[q * 4 + 3] = f.w;
        }
#pragma unroll
        for (int k = 0; k < 16; k++) s[k] += v[k];
        uint16_t h[8];
#pragma unroll
        for (int q = 0; q < 8; q++)
            h[q] = cvt_e4m3x2(v[2 * q] * WSCALE, v[2 * q + 1] * WSCALE);
        uint4 u;
        u.x = (uint32_t)h[0] | ((uint32_t)h[1] << 16);
        u.y = (uint32_t)h[2] | ((uint32_t)h[3] << 16);
        u.z = (uint32_t)h[4] | ((uint32_t)h[5] << 16);
        u.w = (uint32_t)h[6] | ((uint32_t)h[7] << 16);
        int boff = r * 128 + c16 * 16;
        int sw = boff ^ ((boff >> 3) & 0x70);
        *reinterpret_cast<uint4*>(dst + sw) = u;
    }
#pragma unroll
    for (int k = 0; k < 16; k++) cs[tid][k] = s[k];
    __syncthreads();
    for (int step = 128; step >= 8; step >>= 1) {
        if (tid < step) {
#pragma unroll
            for (int k = 0; k < 16; k++) cs[tid][k] += cs[tid + step][k];
        }
        __syncthreads();
    }
    if (tid < 8) {
#pragma unroll
        for (int k = 0; k < 16; k++)
            g_wsumP[(size_t)vb * Hv + kb * 128 + tid * 16 + k] = cs[tid][k];
    }
}

// ---------------- x pass: fp32 -> blocked swizzled e4m3 (+ reset duties) ----------
__global__ void __launch_bounds__(256) convx3_kernel(const float* __restrict__ X) {
    const int tid = threadIdx.x;
    const int kb = blockIdx.x;      // 0..31
    const int mb = blockIdx.y;      // 0..31
    // folded reset: first 64 blocks zero the 1 MB W pad (16 KB each); one thread clears flag
    {
        const int bid = mb * 32 + kb;
        if (bid < 64) {
            uint4* pad = reinterpret_cast<uint4*>(g_W8 + (size_t)250 * 32 * 16384) +
                         (size_t)bid * 1024;
            for (int i = tid; i < 1024; i += 256) pad[i] = make_uint4(0, 0, 0, 0);
        }
        if (bid == 0 && tid == 0) g_fb = 0;
    }
    const float* src = X + (size_t)mb * 128 * Hv + kb * 128;
    unsigned char* dst = g_X8 + ((size_t)(mb * 32 + kb)) * 16384;
    const int c16 = tid & 7;
#pragma unroll
    for (int j = 0; j < 4; j++) {
        int r = (tid >> 3) + j * 32;
        const float4* p = reinterpret_cast<const float4*>(src + (size_t)r * Hv + c16 * 16);
        float v[16];
#pragma unroll
        for (int q = 0; q < 4; q++) {
            float4 f = p[q];
            v[q * 4 + 0] = f.x; v[q * 4 + 1] = f.y; v[q * 4 + 2] = f.z; v[q * 4 + 3] = f.w;
        }
        uint16_t h[8];
#pragma unroll
        for (int q = 0; q < 8; q++)
            h[q] = cvt_e4m3x2(v[2 * q], v[2 * q + 1]);
        uint4 u;
        u.x = (uint32_t)h[0] | ((uint32_t)h[1] << 16);
        u.y = (uint32_t)h[2] | ((uint32_t)h[3] << 16);
        u.z = (uint32_t)h[4] | ((uint32_t)h[5] << 16);
        u.w = (uint32_t)h[6] | ((uint32_t)h[7] << 16);
        int boff = r * 128 + c16 * 16;
        int sw = boff ^ ((boff >> 3) & 0x70);
        *reinterpret_cast<uint4*>(dst + sw) = u;
    }
}

__global__ void wsum_reduce_kernel() {
    int h = blockIdx.x * blockDim.x + threadIdx.x;
    float s = 0.f;
    for (int seg = 0; seg < 250; seg++) s += g_wsumP[(size_t)seg * Hv + h];
    g_wsum[h] = s;
}

// ---------------- fallback-only target kernel (tcgen05 path does this in-GEMM) ----
__global__ void target_fb_kernel(const float* __restrict__ x, const float* __restrict__ W,
                                 const int* __restrict__ tg) {
    if (*(volatile int*)&g_fb == 0) return;
    int warp = threadIdx.x >> 5, lane = threadIdx.x & 31;
    int t = blockIdx.x * 8 + warp;
    if (t < Mv) target_one(x, W, tg, t, lane);
}

// ============================================================================
// tcgen05 FP8 persistent path (arch-specific variant only) — round-14 proven
// ============================================================================
#define NSTAGE 4
#define STAGE_BYTES 32768         // A 16K + B 16K
#define SMEM_HDR 4096             // barriers [8,104) + epi_part [256,2304); DATA at 4096
#define GEMM_SMEM (SMEM_HDR + NSTAGE * STAGE_BYTES)
#define GTHREADS 320              // warps 0-7 epilogue, 8 producer, 9 mma/relay

#if HAS_TCGEN05
__device__ __forceinline__ uint32_t elect_one() {
    uint32_t pred;
    asm volatile("{\n\t.reg .pred p;\n\telect.sync _|p, 0xFFFFFFFF;\n\tselp.b32 %0, 1, 0, p;\n\t}"
                 : "=r"(pred));
    return pred;
}
__device__ __forceinline__ void mbar_init(uint32_t a, uint32_t cnt) {
    asm volatile("mbarrier.init.shared.b64 [%0], %1;" :: "r"(a), "r"(cnt) : "memory");
}
__device__ __forceinline__ void mbar_expect_tx(uint32_t a, uint32_t tx) {
    asm volatile("mbarrier.arrive.expect_tx.shared.b64 _, [%0], %1;" :: "r"(a), "r"(tx) : "memory");
}
__device__ __forceinline__ void mbar_arrive(uint32_t a) {
    asm volatile("mbarrier.arrive.shared.b64 _, [%0];" :: "r"(a) : "memory");
}
__device__ __forceinline__ void mbar_arrive_rank(uint32_t a, uint32_t rank) {
    asm volatile("{\n\t.reg .b32 ra;\n\tmapa.shared::cluster.u32 ra, %0, %1;\n\t"
                 "mbarrier.arrive.shared::cluster.b64 _, [ra];\n\t}" :: "r"(a), "r"(rank) : "memory");
}
__device__ __forceinline__ void mbar_wait(uint32_t a, uint32_t parity) {
    asm volatile(
        "{\n\t.reg .pred P;\n"
        "WL%=:\n\t"
        "mbarrier.try_wait.parity.acquire.cta.shared::cta.b64 P, [%0], %1, 0x989680;\n\t"
        "@P bra WD%=;\n\t"
        "bra WL%=;\n"
        "WD%=:\n\t}"
        :: "r"(a), "r"(parity) : "memory");
}
__device__ __forceinline__ void bulk_g2s(uint32_t dst, const void* src, uint32_t bytes,
                                         uint32_t mbar) {
    asm volatile(
        "cp.async.bulk.shared::cluster.global.mbarrier::complete_tx::bytes [%0], [%1], %2, [%3];"
        :: "r"(dst), "l"(src), "r"(bytes), "r"(mbar) : "memory");
}
__device__ __forceinline__ void bulk_g2s_mc(uint32_t dst, const void* src, uint32_t bytes,
                                            uint32_t mbar, uint16_t mask) {
    asm volatile(
        "cp.async.bulk.shared::cluster.global.mbarrier::complete_tx::bytes.multicast::cluster "
        "[%0], [%1], %2, [%3], %4;"
        :: "r"(dst), "l"(src), "r"(bytes), "r"(mbar), "h"(mask) : "memory");
}
__device__ __forceinline__ void cluster_sync_() {
    asm volatile("barrier.cluster.arrive.aligned;" ::: "memory");
    asm volatile("barrier.cluster.wait.aligned;" ::: "memory");
}
__device__ __forceinline__ void tc_fence_after() {
    asm volatile("tcgen05.fence::after_thread_sync;" ::: "memory");
}
__device__ __forceinline__ void tc_fence_before() {
    asm volatile("tcgen05.fence::before_thread_sync;" ::: "memory");
}
__device__ __forceinline__ void tc_wait_ld() {
    asm volatile("tcgen05.wait::ld.sync.aligned;" ::: "memory");
}
__device__ __forceinline__ void tmem_alloc_cg2(uint32_t smem_addr, uint32_t ncols) {
    asm volatile("tcgen05.alloc.cta_group::2.sync.aligned.shared::cta.b32 [%0], %1;"
                 :: "r"(smem_addr), "r"(ncols) : "memory");
}
__device__ __forceinline__ void tmem_dealloc_cg2(uint32_t tmem, uint32_t ncols) {
    asm volatile("tcgen05.relinquish_alloc_permit.cta_group::2.sync.aligned;");
    asm volatile("tcgen05.dealloc.cta_group::2.sync.aligned.b32 %0, %1;" :: "r"(tmem), "r"(ncols));
}
__device__ __forceinline__ void mma_f8_ss_cg2(uint32_t d_tmem, uint64_t a_desc, uint64_t b_desc,
                                              uint32_t idesc, uint32_t en) {
    asm volatile(
        "{\n\t.reg .pred p;\n\t"
        "setp.ne.u32 p, %6, 0;\n\t"
        "tcgen05.mma.cta_group::2.kind::f8f6f4 [%0], %1, %2, %3, "
        "{%4, %4, %4, %4, %4, %4, %4, %4}, p;\n\t}"
        :: "r"(d_tmem), "l"(a_desc), "l"(b_desc), "r"(idesc),
           "r"(0u), "r"(0u), "r"(en)
        : "memory");
}
__device__ __forceinline__ void commit_mc_cg2(uint32_t mbar, uint16_t mask) {
    asm volatile(
        "tcgen05.commit.cta_group::2.mbarrier::arrive::one.shared::cluster.multicast::cluster.b64 [%0], %1;"
        :: "r"(mbar), "h"(mask) : "memory");
}
__device__ __forceinline__ void ldtm_x32(uint32_t* r, uint32_t addr) {
    asm volatile(
        "tcgen05.ld.sync.aligned.32x32b.x32.b32 "
        "{%0, %1, %2, %3, %4, %5, %6, %7, "
        " %8, %9, %10, %11, %12, %13, %14, %15, "
        " %16, %17, %18, %19, %20, %21, %22, %23, "
        " %24, %25, %26, %27, %28, %29, %30, %31}, [%32];"
        : "=r"(r[0]), "=r"(r[1]), "=r"(r[2]), "=r"(r[3]),
          "=r"(r[4]), "=r"(r[5]), "=r"(r[6]), "=r"(r[7]),
          "=r"(r[8]), "=r"(r[9]), "=r"(r[10]), "=r"(r[11]),
          "=r"(r[12]), "=r"(r[13]), "=r"(r[14]), "=r"(r[15]),
          "=r"(r[16]), "=r"(r[17]), "=r"(r[18]), "=r"(r[19]),
          "=r"(r[20]), "=r"(r[21]), "=r"(r[22]), "=r"(r[23]),
          "=r"(r[24]), "=r"(r[25]), "=r"(r[26]), "=r"(r[27]),
          "=r"(r[28]), "=r"(r[29]), "=r"(r[30]), "=r"(r[31])
        : "r"(addr));
}
__device__ __forceinline__ uint64_t make_desc(uint32_t addr) {
    const uint64_t base = (uint64_t(2) << 61) | (uint64_t(1) << 46) |
                          (uint64_t(64) << 32) | (uint64_t(1) << 16);
    return base | ((uint64_t)(addr >> 4) & 0x3FFF);
}
#endif // HAS_TCGEN05

// Persistent cluster (4,1,1) x 33 (132 CTAs). Per cluster tile: M=512 x N=256.
// Pair p covers M rows [p*256, p*256+256) via one cg2 M=256 MMA per K-step.
// TMEM ping-pong: D buffers at cols 0 and 256; epilogue of tile t overlaps
// MMA of tile t+1. EMPTY committed 0xF by both pair leaders (count=2).
// Epilogue warps compute the exact-fp32 target dots in their pre-loop slack.
__global__ void __launch_bounds__(GTHREADS, 1) __cluster_dims__(4, 1, 1)
gemm_kernel(const float* __restrict__ x, const float* __restrict__ Wp,
            const int* __restrict__ tg) {
#if HAS_TCGEN05
    extern __shared__ char smem[];
    const uint32_t sb = smem_u32(smem);
    float* epi_part = reinterpret_cast<float*>(smem + 256);   // [2][8][32] = 2048B
    const int tid = threadIdx.x;
    const int wid = tid >> 5, lane = tid & 31;
    const int r = blockIdx.x & 3;          // cluster rank
    const int cid = blockIdx.x >> 2;       // cluster id 0..32
    const int p = r >> 1, prank = r & 1;   // pair, rank within pair

    const uint32_t FULL = sb + 8;          // 4 x 8B
    const uint32_t EMPTY = sb + 40;        // 4 x 8B
    const uint32_t TFULL = sb + 72;        // 2 x 8B (MMA done, per TMEM buffer)
    const uint32_t TEPI = sb + 88;         // 2 x 8B (epilogue done, on pair leader)
    const uint32_t DATA = sb + SMEM_HDR;

    const int lo = (cid * TOT_TILES) / NCLUSTERS;
    const int hi = ((cid + 1) * TOT_TILES) / NCLUSTERS;
    const int ntl = hi - lo;

    if (wid == 9) tmem_alloc_cg2(sb, 512);
    if (tid == 0) {
#pragma unroll
        for (int s = 0; s < NSTAGE; s++) {
            mbar_init(FULL + 8 * s, prank ? 1u : 2u);
            mbar_init(EMPTY + 8 * s, 2u);   // commits from BOTH pair leaders
        }
        mbar_init(TFULL + 0, 1u);
        mbar_init(TFULL + 8, 1u);
        mbar_init(TEPI + 0, 2u);
        mbar_init(TEPI + 8, 2u);
    }
    __syncthreads();
    uint32_t tmem;
    asm volatile("ld.shared.b32 %0, [%1];" : "=r"(tmem) : "r"(sb));
    cluster_sync_();

    const uint16_t pair_mask = (p == 0) ? 0x3 : 0xC;

    if (wid == 8) {
        // ---- producer: elected thread streams A + (rank<2) multicast B ----
        if (elect_one()) {
            const uint16_t bmask = prank ? 0xA : 0x5;   // {1,3} : {0,2}
            int git = 0;
            for (int lt = 0; lt < ntl; ++lt) {
                const int t = lo + lt;
                const int tm = t & 7, nt = t >> 3;
                const int rbA = tm * 4 + r;            // A row-tile for this CTA
                const int rbB = nt * 2 + prank;        // B row-tile (ranks 0,1 load)
                for (int it = 0; it < 32; ++it, ++git) {
                    const int slot = git & (NSTAGE - 1);
                    const int u = git >> 2;
                    if (git >= NSTAGE) mbar_wait(EMPTY + 8 * slot, (u + 1) & 1);
                    const uint32_t fb = FULL + 8 * slot;
                    mbar_expect_tx(fb, STAGE_BYTES);
                    const uint32_t d = DATA + slot * STAGE_BYTES;
                    bulk_g2s(d, g_X8 + ((size_t)(rbA * 32 + it)) * 16384, 16384, fb);
                    if (r < 2)
                        bulk_g2s_mc(d + 16384, g_W8 + ((size_t)(rbB * 32 + it)) * 16384,
                                    16384, fb, bmask);
                }
            }
        }
    } else if (wid == 9) {
        if (prank == 1) {
            // ---- relay: forward local stage readiness to pair leader ----
            if (lane == 0) {
                int git = 0;
                for (int lt = 0; lt < ntl; ++lt)
                    for (int it = 0; it < 32; ++it, ++git) {
                        const int slot = git & (NSTAGE - 1);
                        mbar_wait(FULL + 8 * slot, (git >> 2) & 1);
                        mbar_arrive_rank(FULL + 8 * slot, (uint32_t)(r - 1));
                    }
            }
        } else {
            // ---- MMA issuer on pair leaders ----
            const uint32_t IDESC = (1u << 4) | ((256u / 8) << 17) | ((256u / 16) << 24);
            tc_fence_after();
            int git = 0;
            for (int lt = 0; lt < ntl; ++lt) {
                const int dbuf = lt & 1;
                if (lt >= 2) mbar_wait(TEPI + 8 * dbuf, ((lt >> 1) - 1) & 1);
                const uint32_t dt = tmem + dbuf * 256;
                for (int it = 0; it < 32; ++it, ++git) {
                    const int slot = git & (NSTAGE - 1);
                    mbar_wait(FULL + 8 * slot, (git >> 2) & 1);
                    if (elect_one()) {
                        const uint32_t base = DATA + slot * STAGE_BYTES;
                        uint64_t a = make_desc(base);
                        uint64_t b = make_desc(base + 16384);
#pragma unroll
                        for (int k = 0; k < 4; ++k) {
                            uint32_t en = (it | k) ? 1u : 0u;
                            mma_f8_ss_cg2(dt, a + k * 2, b + k * 2, IDESC, en);
                        }
                        commit_mc_cg2(EMPTY + 8 * slot, 0xF);   // couple both pairs
                    }
                }
                if (elect_one()) commit_mc_cg2(TFULL + 8 * dbuf, pair_mask);
            }
        }
    } else {
        // ---- epilogue warps 0-7: target dots in pre-loop slack, then tiles ----
        {
            const int gw = (blockIdx.x << 3) + wid;    // 0..1055
            for (int t = gw; t < Mv; t += 8 * 4 * NCLUSTERS)
                target_one(x, Wp, tg, t, lane);
        }
        const int cgrp = wid >> 2;          // col group: 0 -> [0,128), 1 -> [128,256)
        const int rowloc = (wid & 3) * 32 + lane;
        for (int lt = 0; lt < ntl; ++lt) {
            const int t = lo + lt;
            const int tm = t & 7, nt = t >> 3;
            const int dbuf = lt & 1;
            mbar_wait(TFULL + 8 * dbuf, (lt >> 1) & 1);
            tc_fence_after();
            const uint32_t dbase = tmem + dbuf * 256 + cgrp * 128;
            float s = 0.f;
#pragma unroll
            for (int c2 = 0; c2 < 2; ++c2) {
                uint32_t rg[2][32];
                ldtm_x32(rg[0], dbase + (c2 * 2) * 32);
                ldtm_x32(rg[1], dbase + (c2 * 2 + 1) * 32);
                tc_wait_ld();
#pragma unroll
                for (int i = 0; i < 32; ++i)
                    s += __expf(__uint_as_float(rg[0][i]) * WISCALE) +
                         __expf(__uint_as_float(rg[1][i]) * WISCALE);
            }
            tc_fence_before();
            epi_part[(dbuf * 8 + wid) * 32 + lane] = s;
            asm volatile("bar.sync 1, 256;" ::: "memory");
            if (wid < 4) {
                const int token = tm * 512 + p * 256 + prank * 128 + rowloc;
                float tot = s + epi_part[(dbuf * 8 + wid + 4) * 32 + lane];
                g_sumexp[(size_t)nt * Mv + token] = tot;
            }
            if (tid == 0) {
                if (prank == 0) mbar_arrive(TEPI + 8 * dbuf);
                else            mbar_arrive_rank(TEPI + 8 * dbuf, (uint32_t)(r - 1));
            }
        }
    }

    __syncthreads();
    if (wid == 9) tmem_dealloc_cg2(tmem, 512);
    cluster_sync_();
#else
    (void)x; (void)Wp; (void)tg;
    if (threadIdx.x == 0 && blockIdx.x == 0) g_fb = 1;
#endif
}

// ============================================================================
// Fallback mma.sync GEMM (runs only if g_fb == 1); converts fp8 -> bf16 on load.
// ============================================================================
#define ASTRIDE 40

__global__ void __launch_bounds__(256) gemm_fb_kernel() {
    if (*(volatile int*)&g_fb == 0) return;
    __shared__ __nv_bfloat16 As[128 * ASTRIDE];
    __shared__ __nv_bfloat16 Bs[128 * ASTRIDE];
    __shared__ float rsum[2][128];

    const int tid = threadIdx.x;
    const int m0 = blockIdx.x * 128;
    const int n0 = blockIdx.y * 128;
    const int warp = tid >> 5, lane = tid & 31;
    const int mw = warp >> 1, nw = warp & 1;

    float acc[2][8][4];
#pragma unroll
    for (int a = 0; a < 2; a++)
#pragma unroll
        for (int b = 0; b < 8; b++)
#pragma unroll
            for (int c = 0; c < 4; c++) acc[a][b][c] = 0.f;

    uint2 pa[4], pb[4];
    auto loadG = [&](int kk) {
#pragma unroll
        for (int j = 0; j < 4; j++) {
            int i = tid + j * 256;
            int row = i >> 3, seg = i & 7;
            pa[j] = ld_blk8(g_X8, m0 + row, kk + seg * 4, 1.0f);
            pb[j] = ld_blk8(g_W8, n0 + row, kk + seg * 4, WISCALE);
        }
    };
    auto storeS = [&]() {
#pragma unroll
        for (int j = 0; j < 4; j++) {
            int i = tid + j * 256;
            int row = i >> 3, seg = i & 7;
            *reinterpret_cast<uint2*>(As + row * ASTRIDE + seg * 4) = pa[j];
            *reinterpret_cast<uint2*>(Bs + row * ASTRIDE + seg * 4) = pb[j];
        }
    };

    loadG(0);
    storeS();

    for (int it = 0; it < 128; ++it) {
        __syncthreads();
        if (it + 1 < 128) loadG((it + 1) * 32);

#pragma unroll
        for (int ks = 0; ks < 32; ks += 16) {
            uint32_t a[2][4];
#pragma unroll
            for (int mt = 0; mt < 2; mt++) {
                int row = mw * 32 + mt * 16 + (lane & 15);
                int col = ks + ((lane >> 4) << 3);
                uint32_t addr = smem_u32(As + row * ASTRIDE + col);
                asm volatile(
                    "ldmatrix.sync.aligned.m8n8.x4.shared.b16 {%0,%1,%2,%3}, [%4];"
                    : "=r"(a[mt][0]), "=r"(a[mt][1]), "=r"(a[mt][2]), "=r"(a[mt][3])
                    : "r"(addr));
            }
            uint32_t b[8][2];
#pragma unroll
            for (int np = 0; np < 4; np++) {
                int n = nw * 64 + np * 16 + (lane & 7) + ((lane >> 4) << 3);
                int kq = ks + (((lane >> 3) & 1) << 3);
                uint32_t addr = smem_u32(Bs + n * ASTRIDE + kq);
                asm volatile(
                    "ldmatrix.sync.aligned.m8n8.x4.shared.b16 {%0,%1,%2,%3}, [%4];"
                    : "=r"(b[2 * np][0]), "=r"(b[2 * np][1]),
                      "=r"(b[2 * np + 1][0]), "=r"(b[2 * np + 1][1])
                    : "r"(addr));
            }
#pragma unroll
            for (int mt = 0; mt < 2; mt++)
#pragma unroll
                for (int nt = 0; nt < 8; nt++) {
                    float* c = acc[mt][nt];
                    asm volatile(
                        "mma.sync.aligned.m16n8k16.row.col.f32.bf16.bf16.f32 "
                        "{%0,%1,%2,%3}, {%4,%5,%6,%7}, {%8,%9}, {%0,%1,%2,%3};"
                        : "+f"(c[0]), "+f"(c[1]), "+f"(c[2]), "+f"(c[3])
                        : "r"(a[mt][0]), "r"(a[mt][1]), "r"(a[mt][2]), "r"(a[mt][3]),
                          "r"(b[nt][0]), "r"(b[nt][1]));
                }
        }
        __syncthreads();
        if (it + 1 < 128) storeS();
    }

#pragma unroll
    for (int mt = 0; mt < 2; mt++) {
        float slo = 0.f, shi = 0.f;
#pragma unroll
        for (int nt = 0; nt < 8; nt++) {
            slo += __expf(acc[mt][nt][0]) + __expf(acc[mt][nt][1]);
            shi += __expf(acc[mt][nt][2]) + __expf(acc[mt][nt][3]);
        }
        slo += __shfl_xor_sync(0xFFFFFFFFu, slo, 1);
        slo += __shfl_xor_sync(0xFFFFFFFFu, slo, 2);
        shi += __shfl_xor_sync(0xFFFFFFFFu, shi, 1);
        shi += __shfl_xor_sync(0xFFFFFFFFu, shi, 2);
        if ((lane & 3) == 0) {
            int rr = mw * 32 + mt * 16 + (lane >> 2);
            rsum[nw][rr] = slo;
            rsum[nw][rr + 8] = shi;
        }
    }
    __syncthreads();
    if (tid < 128) {
        g_sumexp[(size_t)blockIdx.y * Mv + m0 + tid] = rsum[0][tid] + rsum[1][tid];
    }
}

// ---------------- per-token logp ----------------
__global__ void token_reduce_kernel(const int* __restrict__ tg) {
    int t = blockIdx.x * blockDim.x + threadIdx.x;
    if (t >= Mv) return;
    const int fb = g_fb;
    const int rows = fb ? NROWS : NTILE_TC;   // read exactly what was written
    float s = 0.f;
    for (int c = 0; c < rows; c++) s += g_sumexp[(size_t)c * Mv + t];
    if (fb == 0) s -= 256.0f;   // tcgen05 path: 256 zero-logit pad columns
    g_logp[t] = (tg[t] != IGNORE_INDEX) ? (g_tgt[t] - logf(s)) : 0.f;
}

// ---------------- final loss / outputs ----------------
__global__ void final_kernel(const int* __restrict__ tg, float* __restrict__ out) {
    __shared__ float red[256];
    __shared__ int redi[256];
    __shared__ float seq[8];
    __shared__ float xw[2];
    int tid = threadIdx.x;

    for (int s = 0; s < 8; s++) {
        float v = 0.f; int c = 0;
        for (int i = tid; i < Sv; i += 256) {
            int t = s * Sv + i;
            v += g_logp[t];
            c += (tg[t] != IGNORE_INDEX);
        }
        red[tid] = v; redi[tid] = c;
        __syncthreads();
        for (int o = 128; o; o >>= 1) {
            if (tid < o) { red[tid] += red[tid + o]; redi[tid] += redi[tid + o]; }
            __syncthreads();
        }
        if (tid == 0) seq[s] = red[0] / (float)redi[0];
        __syncthreads();
    }

    for (int h = 0; h < 2; h++) {
        float v = 0.f;
        for (int i = tid; i < 4 * Sv; i += 256) v += g_xdw[h * 4 * Sv + i];
        red[tid] = v;
        __syncthreads();
        for (int o = 128; o; o >>= 1) {
            if (tid < o) red[tid] += red[tid + o];
            __syncthreads();
        }
        if (tid == 0) xw[h] = red[0];
        __syncthreads();
    }

    if (tid == 0) {
        float loss = 0.f;
#pragma unroll
        for (int i = 0; i < 4; i++) {
            float z = 0.1f * (seq[i] - seq[4 + i]);
            float ls = fminf(z, 0.f) - log1pf(expf(-fabsf(z)));   // log_sigmoid(z)
            loss += -ls;
        }
        loss *= 0.25f;
        out[0] = loss;
#pragma unroll
        for (int i = 0; i < 8; i++) out[1 + i] = seq[i];
        const float denom = 4.0f * (float)Sv * (float)Vv;
        out[9] = xw[0] / denom;
        out[10] = xw[1] / denom;
        out[11] = 0.0f;
    }
}

// ---------------- launch ----------------
extern "C" void kernel_launch(void* const* d_in, const int* in_sizes, int n_in,
                              void* d_out, int out_size) {
    const float* x = nullptr;
    const float* W = nullptr;
    const int* tg = nullptr;
    for (int i = 0; i < n_in; i++) {
        if (in_sizes[i] == Vv * Hv) W = (const float*)d_in[i];
        else if (in_sizes[i] == Mv * Hv) x = (const float*)d_in[i];
        else if (in_sizes[i] == Mv) tg = (const int*)d_in[i];
    }
    float* out = (float*)d_out;

    cudaFuncSetAttribute(gemm_kernel, cudaFuncAttributeMaxDynamicSharedMemorySize, GEMM_SMEM);

    wpass3_kernel<<<dim3(32, 250), 256>>>(W);                 // 1
    convx3_kernel<<<dim3(32, 32), 256>>>(x);                  // 2 (+reset duties)
    wsum_reduce_kernel<<<16, 256>>>();                        // 3 (g_wsum before gemm)
    gemm_kernel<<<4 * NCLUSTERS, GTHREADS, GEMM_SMEM>>>(x, W, tg); // 4 (+in-GEMM target)
    target_fb_kernel<<<512, 256>>>(x, W, tg);                 // 5 (no-op if tcgen05 ran)
    gemm_fb_kernel<<<dim3(32, 250), 256>>>();                 // 6 (no-op if tcgen05 ran)
    token_reduce_kernel<<<32, 128>>>(tg);                     // 7
    final_kernel<<<1, 256>>>(tg, out);                        // 8
}

// round 16
// speedup vs baseline: 1.1869x; 1.0182x over previous
#include <cuda_runtime.h>
#include <cuda_bf16.h>
#include <cuda_fp8.h>
#include <cstdint>

// Problem constants
#define Hv 4096
#define Vv 32000
#define Mv 4096          // B*S tokens
#define Sv 512
#define NROWS 250        // fallback sum-exp rows; tcgen05 path uses 126
#define NTILE_TC 126     // V padded to 32256 = 126 * 256
#define IGNORE_INDEX (-100)
#define WSCALE 64.0f
#define WISCALE 0.015625f
#define NCLUSTERS 33     // 132 CTAs — proven single-wave packing
#define TOT_TILES (8 * NTILE_TC)   // 1008: tm fastest (8 of M=512), nt = t>>3

#if defined(__CUDA_ARCH_FEAT_SM103_ALL) || defined(__CUDA_ARCH_FEAT_SM100_ALL) || \
    (defined(__CUDA_ARCH_FAMILY_SPECIFIC__) && (__CUDA_ARCH_FAMILY_SPECIFIC__ >= 1000))
#define HAS_TCGEN05 1
#else
#define HAS_TCGEN05 0
#endif

// ---------------- device scratch ----------------
__device__ __align__(128) unsigned char g_W8[(size_t)252 * 32 * 16384];  // 132 MB (2 pad row-tiles)
__device__ __align__(128) unsigned char g_X8[(size_t)32 * 32 * 16384];   // 16 MB
__device__ float g_wsumP[(size_t)250 * Hv];
__device__ float g_wsum[Hv];
__device__ float g_tgt[Mv];
__device__ float g_xdw[Mv];
__device__ float g_sumexp[(size_t)NROWS * Mv];
__device__ float g_logp[Mv];
__device__ int g_fb;   // 1 -> tcgen05 unavailable, mma.sync fallback must run

// ---------------- generic helpers ----------------
__device__ __forceinline__ uint32_t smem_u32(const void* p) {
    return (uint32_t)__cvta_generic_to_shared(p);
}
__device__ __forceinline__ uint16_t cvt_e4m3x2(float lo, float hi) {
    uint16_t r;
    asm("cvt.rn.satfinite.e4m3x2.f32 %0, %1, %2;" : "=h"(r) : "f"(hi), "f"(lo));
    return r;
}

// warp-cooperative target dot: g_tgt[t] = x[t].W[safe_tgt], g_xdw[t] = x[t].wsum
__device__ __forceinline__ void target_one(const float* __restrict__ x,
                                           const float* __restrict__ W,
                                           const int* __restrict__ tg,
                                           int t, int lane) {
    int tv = tg[t];
    int safe = tv < 0 ? 0 : (tv >= Vv ? Vv - 1 : tv);
    const float4* xr = reinterpret_cast<const float4*>(x + (size_t)t * Hv);
    const float4* wr = reinterpret_cast<const float4*>(W + (size_t)safe * Hv);
    const float4* sr = reinterpret_cast<const float4*>(g_wsum);
    float d1 = 0.f, d2 = 0.f;
#pragma unroll 4
    for (int i = lane; i < Hv / 4; i += 32) {
        float4 a = xr[i], b = wr[i], c = sr[i];
        d1 += a.x * b.x + a.y * b.y + a.z * b.z + a.w * b.w;
        d2 += a.x * c.x + a.y * c.y + a.z * c.z + a.w * c.w;
    }
#pragma unroll
    for (int o = 16; o; o >>= 1) {
        d1 += __shfl_xor_sync(0xFFFFFFFFu, d1, o);
        d2 += __shfl_xor_sync(0xFFFFFFFFu, d2, o);
    }
    if (lane == 0) { g_tgt[t] = d1; g_xdw[t] = d2; }
}

// fallback loader: 4 fp8 at (row, k) [k%4==0] -> 4 bf16 (scaled)
__device__ __forceinline__ uint2 ld_blk8(const unsigned char* base, int row, int k, float scale) {
    size_t tile = ((size_t)(row >> 7) * 32 + (k >> 7)) * 16384;
    int rr = row & 127, cc = k & 127;
    int chunk = rr * 128 + (cc >> 4) * 16;
    int sw = chunk ^ ((chunk >> 3) & 0x70);
    uint32_t v = *reinterpret_cast<const uint32_t*>(base + tile + (size_t)sw + (cc & 15));
    __nv_bfloat16 b[4];
#pragma unroll
    for (int i = 0; i < 4; i++) {
        __nv_fp8_storage_t fs = (__nv_fp8_storage_t)((v >> (8 * i)) & 0xFF);
        __half_raw hr = __nv_cvt_fp8_to_halfraw(fs, __NV_E4M3);
        float f = __half2float(*reinterpret_cast<__half*>(&hr)) * scale;
        b[i] = __float2bfloat16(f);
    }
    uint2 r;
    r.x = *reinterpret_cast<uint32_t*>(&b[0]);
    r.y = *reinterpret_cast<uint32_t*>(&b[2]);
    return r;
}

// ---------------- W pass: fp32 -> blocked swizzled e4m3 (x64) + col partial sums ----
__global__ void __launch_bounds__(256) wpass3_kernel(const float* __restrict__ W) {
    __shared__ float cs[256][17];   // padded: conflict-free column-sum reduction
    const int tid = threadIdx.x;
    const int kb = blockIdx.x;      // 0..31 (128 K each)
    const int vb = blockIdx.y;      // 0..249 (128 rows each)
    const float* src = W + (size_t)vb * 128 * Hv + kb * 128;
    unsigned char* dst = g_W8 + ((size_t)(vb * 32 + kb)) * 16384;
    const int c16 = tid & 7;
    float s[16];
#pragma unroll
    for (int k = 0; k < 16; k++) s[k] = 0.f;
#pragma unroll
    for (int j = 0; j < 4; j++) {
        int r = (tid >> 3) + j * 32;
        const float4* p = reinterpret_cast<const float4*>(src + (size_t)r * Hv + c16 * 16);
        float v[16];
#pragma unroll
        for (int q = 0; q < 4; q++) {
            float4 f = p[q];
            v[q * 4 + 0] = f.x; v[q * 4 + 1] = f.y; v[q * 4 + 2] = f.z; v[q * 4 + 3] = f.w;
        }
#pragma unroll
        for (int k = 0; k < 16; k++) s[k] += v[k];
        uint16_t h[8];
#pragma unroll
        for (int q = 0; q < 8; q++)
            h[q] = cvt_e4m3x2(v[2 * q] * WSCALE, v[2 * q + 1] * WSCALE);
        uint4 u;
        u.x = (uint32_t)h[0] | ((uint32_t)h[1] << 16);
        u.y = (uint32_t)h[2] | ((uint32_t)h[3] << 16);
        u.z = (uint32_t)h[4] | ((uint32_t)h[5] << 16);
        u.w = (uint32_t)h[6] | ((uint32_t)h[7] << 16);
        int boff = r * 128 + c16 * 16;
        int sw = boff ^ ((boff >> 3) & 0x70);
        *reinterpret_cast<uint4*>(dst + sw) = u;
    }
#pragma unroll
    for (int k = 0; k < 16; k++) cs[tid][k] = s[k];
    __syncthreads();
    for (int step = 128; step >= 8; step >>= 1) {
        if (tid < step) {
#pragma unroll
            for (int k = 0; k < 16; k++) cs[tid][k] += cs[tid + step][k];
        }
        __syncthreads();
    }
    if (tid < 8) {
#pragma unroll
        for (int k = 0; k < 16; k++)
            g_wsumP[(size_t)vb * Hv + kb * 128 + tid * 16 + k] = cs[tid][k];
    }
}

// ---------------- x pass: fp32 -> blocked swizzled e4m3 (+ reset duties) ----------
__global__ void __launch_bounds__(256) convx3_kernel(const float* __restrict__ X) {
    const int tid = threadIdx.x;
    const int kb = blockIdx.x;      // 0..31
    const int mb = blockIdx.y;      // 0..31
    {
        const int bid = mb * 32 + kb;
        if (bid < 64) {
            uint4* pad = reinterpret_cast<uint4*>(g_W8 + (size_t)250 * 32 * 16384) +
                         (size_t)bid * 1024;
            for (int i = tid; i < 1024; i += 256) pad[i] = make_uint4(0, 0, 0, 0);
        }
        if (bid == 0 && tid == 0) g_fb = 0;
    }
    const float* src = X + (size_t)mb * 128 * Hv + kb * 128;
    unsigned char* dst = g_X8 + ((size_t)(mb * 32 + kb)) * 16384;
    const int c16 = tid & 7;
#pragma unroll
    for (int j = 0; j < 4; j++) {
        int r = (tid >> 3) + j * 32;
        const float4* p = reinterpret_cast<const float4*>(src + (size_t)r * Hv + c16 * 16);
        float v[16];
#pragma unroll
        for (int q = 0; q < 4; q++) {
            float4 f = p[q];
            v[q * 4 + 0] = f.x; v[q * 4 + 1] = f.y; v[q * 4 + 2] = f.z; v[q * 4 + 3] = f.w;
        }
        uint16_t h[8];
#pragma unroll
        for (int q = 0; q < 8; q++)
            h[q] = cvt_e4m3x2(v[2 * q], v[2 * q + 1]);
        uint4 u;
        u.x = (uint32_t)h[0] | ((uint32_t)h[1] << 16);
        u.y = (uint32_t)h[2] | ((uint32_t)h[3] << 16);
        u.z = (uint32_t)h[4] | ((uint32_t)h[5] << 16);
        u.w = (uint32_t)h[6] | ((uint32_t)h[7] << 16);
        int boff = r * 128 + c16 * 16;
        int sw = boff ^ ((boff >> 3) & 0x70);
        *reinterpret_cast<uint4*>(dst + sw) = u;
    }
}

__global__ void wsum_reduce_kernel() {
    int h = blockIdx.x * blockDim.x + threadIdx.x;
    float s = 0.f;
    for (int seg = 0; seg < 250; seg++) s += g_wsumP[(size_t)seg * Hv + h];
    g_wsum[h] = s;
}

// ---------------- fallback-only target kernel (tcgen05 path does this in-GEMM) ----
__global__ void target_fb_kernel(const float* __restrict__ x, const float* __restrict__ W,
                                 const int* __restrict__ tg) {
    if (*(volatile int*)&g_fb == 0) return;
    int warp = threadIdx.x >> 5, lane = threadIdx.x & 31;
    int t = blockIdx.x * 8 + warp;
    if (t < Mv) target_one(x, W, tg, t, lane);
}

// ============================================================================
// tcgen05 FP8 persistent path (arch-specific variant only)
// Round-15 proven pipeline, NSTAGE deepened 4 -> 6 (ncu: tensor=71%,
// mem far from saturated => FULL-latency bubbles; 6 stages cover 3072
// MMA-cycles > measured TMA round-trip).
// ============================================================================
#define NSTAGE 6
#define STAGE_BYTES 32768         // A 16K + B 16K
#define SMEM_HDR 4096             // barriers [8,120) + epi_part [256,2304); DATA at 4096
#define GEMM_SMEM (SMEM_HDR + NSTAGE * STAGE_BYTES)   // 200704 <= 227KB
#define GTHREADS 320              // warps 0-7 epilogue, 8 producer, 9 mma/relay

#if HAS_TCGEN05
__device__ __forceinline__ uint32_t elect_one() {
    uint32_t pred;
    asm volatile("{\n\t.reg .pred p;\n\telect.sync _|p, 0xFFFFFFFF;\n\tselp.b32 %0, 1, 0, p;\n\t}"
                 : "=r"(pred));
    return pred;
}
__device__ __forceinline__ void mbar_init(uint32_t a, uint32_t cnt) {
    asm volatile("mbarrier.init.shared.b64 [%0], %1;" :: "r"(a), "r"(cnt) : "memory");
}
__device__ __forceinline__ void mbar_expect_tx(uint32_t a, uint32_t tx) {
    asm volatile("mbarrier.arrive.expect_tx.shared.b64 _, [%0], %1;" :: "r"(a), "r"(tx) : "memory");
}
__device__ __forceinline__ void mbar_arrive(uint32_t a) {
    asm volatile("mbarrier.arrive.shared.b64 _, [%0];" :: "r"(a) : "memory");
}
__device__ __forceinline__ void mbar_arrive_rank(uint32_t a, uint32_t rank) {
    asm volatile("{\n\t.reg .b32 ra;\n\tmapa.shared::cluster.u32 ra, %0, %1;\n\t"
                 "mbarrier.arrive.shared::cluster.b64 _, [ra];\n\t}" :: "r"(a), "r"(rank) : "memory");
}
__device__ __forceinline__ void mbar_wait(uint32_t a, uint32_t parity) {
    asm volatile(
        "{\n\t.reg .pred P;\n"
        "WL%=:\n\t"
        "mbarrier.try_wait.parity.acquire.cta.shared::cta.b64 P, [%0], %1, 0x989680;\n\t"
        "@P bra WD%=;\n\t"
        "bra WL%=;\n"
        "WD%=:\n\t}"
        :: "r"(a), "r"(parity) : "memory");
}
__device__ __forceinline__ void bulk_g2s(uint32_t dst, const void* src, uint32_t bytes,
                                         uint32_t mbar) {
    asm volatile(
        "cp.async.bulk.shared::cluster.global.mbarrier::complete_tx::bytes [%0], [%1], %2, [%3];"
        :: "r"(dst), "l"(src), "r"(bytes), "r"(mbar) : "memory");
}
__device__ __forceinline__ void bulk_g2s_mc(uint32_t dst, const void* src, uint32_t bytes,
                                            uint32_t mbar, uint16_t mask) {
    asm volatile(
        "cp.async.bulk.shared::cluster.global.mbarrier::complete_tx::bytes.multicast::cluster "
        "[%0], [%1], %2, [%3], %4;"
        :: "r"(dst), "l"(src), "r"(bytes), "r"(mbar), "h"(mask) : "memory");
}
__device__ __forceinline__ void cluster_sync_() {
    asm volatile("barrier.cluster.arrive.aligned;" ::: "memory");
    asm volatile("barrier.cluster.wait.aligned;" ::: "memory");
}
__device__ __forceinline__ void tc_fence_after() {
    asm volatile("tcgen05.fence::after_thread_sync;" ::: "memory");
}
__device__ __forceinline__ void tc_fence_before() {
    asm volatile("tcgen05.fence::before_thread_sync;" ::: "memory");
}
__device__ __forceinline__ void tc_wait_ld() {
    asm volatile("tcgen05.wait::ld.sync.aligned;" ::: "memory");
}
__device__ __forceinline__ void tmem_alloc_cg2(uint32_t smem_addr, uint32_t ncols) {
    asm volatile("tcgen05.alloc.cta_group::2.sync.aligned.shared::cta.b32 [%0], %1;"
                 :: "r"(smem_addr), "r"(ncols) : "memory");
}
__device__ __forceinline__ void tmem_dealloc_cg2(uint32_t tmem, uint32_t ncols) {
    asm volatile("tcgen05.relinquish_alloc_permit.cta_group::2.sync.aligned;");
    asm volatile("tcgen05.dealloc.cta_group::2.sync.aligned.b32 %0, %1;" :: "r"(tmem), "r"(ncols));
}
__device__ __forceinline__ void mma_f8_ss_cg2(uint32_t d_tmem, uint64_t a_desc, uint64_t b_desc,
                                              uint32_t idesc, uint32_t en) {
    asm volatile(
        "{\n\t.reg .pred p;\n\t"
        "setp.ne.u32 p, %6, 0;\n\t"
        "tcgen05.mma.cta_group::2.kind::f8f6f4 [%0], %1, %2, %3, "
        "{%4, %4, %4, %4, %4, %4, %4, %4}, p;\n\t}"
        :: "r"(d_tmem), "l"(a_desc), "l"(b_desc), "r"(idesc),
           "r"(0u), "r"(0u), "r"(en)
        : "memory");
}
__device__ __forceinline__ void commit_mc_cg2(uint32_t mbar, uint16_t mask) {
    asm volatile(
        "tcgen05.commit.cta_group::2.mbarrier::arrive::one.shared::cluster.multicast::cluster.b64 [%0], %1;"
        :: "r"(mbar), "h"(mask) : "memory");
}
__device__ __forceinline__ void ldtm_x32(uint32_t* r, uint32_t addr) {
    asm volatile(
        "tcgen05.ld.sync.aligned.32x32b.x32.b32 "
        "{%0, %1, %2, %3, %4, %5, %6, %7, "
        " %8, %9, %10, %11, %12, %13, %14, %15, "
        " %16, %17, %18, %19, %20, %21, %22, %23, "
        " %24, %25, %26, %27, %28, %29, %30, %31}, [%32];"
        : "=r"(r[0]), "=r"(r[1]), "=r"(r[2]), "=r"(r[3]),
          "=r"(r[4]), "=r"(r[5]), "=r"(r[6]), "=r"(r[7]),
          "=r"(r[8]), "=r"(r[9]), "=r"(r[10]), "=r"(r[11]),
          "=r"(r[12]), "=r"(r[13]), "=r"(r[14]), "=r"(r[15]),
          "=r"(r[16]), "=r"(r[17]), "=r"(r[18]), "=r"(r[19]),
          "=r"(r[20]), "=r"(r[21]), "=r"(r[22]), "=r"(r[23]),
          "=r"(r[24]), "=r"(r[25]), "=r"(r[26]), "=r"(r[27]),
          "=r"(r[28]), "=r"(r[29]), "=r"(r[30]), "=r"(r[31])
        : "r"(addr));
}
__device__ __forceinline__ uint64_t make_desc(uint32_t addr) {
    const uint64_t base = (uint64_t(2) << 61) | (uint64_t(1) << 46) |
                          (uint64_t(64) << 32) | (uint64_t(1) << 16);
    return base | ((uint64_t)(addr >> 4) & 0x3FFF);
}
#endif // HAS_TCGEN05

// Persistent cluster (4,1,1) x 33 (132 CTAs). Per cluster tile: M=512 x N=256.
// Pair p covers M rows [p*256, p*256+256) via one cg2 M=256 MMA per K-step.
// TMEM ping-pong: D buffers at cols 0 and 256; epilogue of tile t overlaps
// MMA of tile t+1. EMPTY committed 0xF by both pair leaders (count=2).
// 6-stage SMEM ring (incremental slot/phase counters — NSTAGE not pow2).
// Epilogue warps compute the exact-fp32 target dots in their pre-loop slack.
__global__ void __launch_bounds__(GTHREADS, 1) __cluster_dims__(4, 1, 1)
gemm_kernel(const float* __restrict__ x, const float* __restrict__ Wp,
            const int* __restrict__ tg) {
#if HAS_TCGEN05
    extern __shared__ char smem[];
    const uint32_t sb = smem_u32(smem);
    float* epi_part = reinterpret_cast<float*>(smem + 256);   // [2][8][32] = 2048B
    const int tid = threadIdx.x;
    const int wid = tid >> 5, lane = tid & 31;
    const int r = blockIdx.x & 3;          // cluster rank
    const int cid = blockIdx.x >> 2;       // cluster id 0..32
    const int p = r >> 1, prank = r & 1;   // pair, rank within pair

    const uint32_t FULL = sb + 8;          // NSTAGE x 8B
    const uint32_t EMPTY = sb + 8 + 8 * NSTAGE;
    const uint32_t TFULL = sb + 8 + 16 * NSTAGE;   // 2 x 8B
    const uint32_t TEPI = sb + 24 + 16 * NSTAGE;   // 2 x 8B
    const uint32_t DATA = sb + SMEM_HDR;

    const int lo = (cid * TOT_TILES) / NCLUSTERS;
    const int hi = ((cid + 1) * TOT_TILES) / NCLUSTERS;
    const int ntl = hi - lo;

    if (wid == 9) tmem_alloc_cg2(sb, 512);
    if (tid == 0) {
#pragma unroll
        for (int s = 0; s < NSTAGE; s++) {
            mbar_init(FULL + 8 * s, prank ? 1u : 2u);
            mbar_init(EMPTY + 8 * s, 2u);   // commits from BOTH pair leaders
        }
        mbar_init(TFULL + 0, 1u);
        mbar_init(TFULL + 8, 1u);
        mbar_init(TEPI + 0, 2u);
        mbar_init(TEPI + 8, 2u);
    }
    __syncthreads();
    uint32_t tmem;
    asm volatile("ld.shared.b32 %0, [%1];" : "=r"(tmem) : "r"(sb));
    cluster_sync_();

    const uint16_t pair_mask = (p == 0) ? 0x3 : 0xC;

    if (wid == 8) {
        // ---- producer: elected thread streams A + (rank<2) multicast B ----
        if (elect_one()) {
            const uint16_t bmask = prank ? 0xA : 0x5;   // {1,3} : {0,2}
            int git = 0, slot = 0, phb = 0;
            for (int lt = 0; lt < ntl; ++lt) {
                const int t = lo + lt;
                const int tm = t & 7, nt = t >> 3;
                const int rbA = tm * 4 + r;            // A row-tile for this CTA
                const int rbB = nt * 2 + prank;        // B row-tile (ranks 0,1 load)
                for (int it = 0; it < 32; ++it, ++git) {
                    if (git >= NSTAGE) mbar_wait(EMPTY + 8 * slot, phb ^ 1);
                    const uint32_t fb = FULL + 8 * slot;
                    mbar_expect_tx(fb, STAGE_BYTES);
                    const uint32_t d = DATA + slot * STAGE_BYTES;
                    bulk_g2s(d, g_X8 + ((size_t)(rbA * 32 + it)) * 16384, 16384, fb);
                    if (r < 2)
                        bulk_g2s_mc(d + 16384, g_W8 + ((size_t)(rbB * 32 + it)) * 16384,
                                    16384, fb, bmask);
                    if (++slot == NSTAGE) { slot = 0; phb ^= 1; }
                }
            }
        }
    } else if (wid == 9) {
        if (prank == 1) {
            // ---- relay: forward local stage readiness to pair leader ----
            if (lane == 0) {
                int slot = 0, phb = 0;
                const int total = ntl * 32;
                for (int g = 0; g < total; ++g) {
                    mbar_wait(FULL + 8 * slot, phb);
                    mbar_arrive_rank(FULL + 8 * slot, (uint32_t)(r - 1));
                    if (++slot == NSTAGE) { slot = 0; phb ^= 1; }
                }
            }
        } else {
            // ---- MMA issuer on pair leaders ----
            const uint32_t IDESC = (1u << 4) | ((256u / 8) << 17) | ((256u / 16) << 24);
            tc_fence_after();
            int slot = 0, phb = 0;
            for (int lt = 0; lt < ntl; ++lt) {
                const int dbuf = lt & 1;
                if (lt >= 2) mbar_wait(TEPI + 8 * dbuf, ((lt >> 1) - 1) & 1);
                const uint32_t dt = tmem + dbuf * 256;
                for (int it = 0; it < 32; ++it) {
                    mbar_wait(FULL + 8 * slot, phb);
                    if (elect_one()) {
                        const uint32_t base = DATA + slot * STAGE_BYTES;
                        uint64_t a = make_desc(base);
                        uint64_t b = make_desc(base + 16384);
#pragma unroll
                        for (int k = 0; k < 4; ++k) {
                            uint32_t en = (it | k) ? 1u : 0u;
                            mma_f8_ss_cg2(dt, a + k * 2, b + k * 2, IDESC, en);
                        }
                        commit_mc_cg2(EMPTY + 8 * slot, 0xF);   // couple both pairs
                    }
                    if (++slot == NSTAGE) { slot = 0; phb ^= 1; }
                }
                if (elect_one()) commit_mc_cg2(TFULL + 8 * dbuf, pair_mask);
            }
        }
    } else {
        // ---- epilogue warps 0-7: target dots in pre-loop slack, then tiles ----
        {
            const int gw = (blockIdx.x << 3) + wid;    // 0..1055
            for (int t = gw; t < Mv; t += 8 * 4 * NCLUSTERS)
                target_one(x, Wp, tg, t, lane);
        }
        const int cgrp = wid >> 2;          // col group: 0 -> [0,128), 1 -> [128,256)
        const int rowloc = (wid & 3) * 32 + lane;
        for (int lt = 0; lt < ntl; ++lt) {
            const int t = lo + lt;
            const int tm = t & 7, nt = t >> 3;
            const int dbuf = lt & 1;
            mbar_wait(TFULL + 8 * dbuf, (lt >> 1) & 1);
            tc_fence_after();
            const uint32_t dbase = tmem + dbuf * 256 + cgrp * 128;
            float s = 0.f;
#pragma unroll
            for (int c2 = 0; c2 < 2; ++c2) {
                uint32_t rg[2][32];
                ldtm_x32(rg[0], dbase + (c2 * 2) * 32);
                ldtm_x32(rg[1], dbase + (c2 * 2 + 1) * 32);
                tc_wait_ld();
#pragma unroll
                for (int i = 0; i < 32; ++i)
                    s += __expf(__uint_as_float(rg[0][i]) * WISCALE) +
                         __expf(__uint_as_float(rg[1][i]) * WISCALE);
            }
            tc_fence_before();
            epi_part[(dbuf * 8 + wid) * 32 + lane] = s;
            asm volatile("bar.sync 1, 256;" ::: "memory");
            if (wid < 4) {
                const int token = tm * 512 + p * 256 + prank * 128 + rowloc;
                float tot = s + epi_part[(dbuf * 8 + wid + 4) * 32 + lane];
                g_sumexp[(size_t)nt * Mv + token] = tot;
            }
            if (tid == 0) {
                if (prank == 0) mbar_arrive(TEPI + 8 * dbuf);
                else            mbar_arrive_rank(TEPI + 8 * dbuf, (uint32_t)(r - 1));
            }
        }
    }

    __syncthreads();
    if (wid == 9) tmem_dealloc_cg2(tmem, 512);
    cluster_sync_();
#else
    (void)x; (void)Wp; (void)tg;
    if (threadIdx.x == 0 && blockIdx.x == 0) g_fb = 1;
#endif
}

// ============================================================================
// Fallback mma.sync GEMM (runs only if g_fb == 1); converts fp8 -> bf16 on load.
// ============================================================================
#define ASTRIDE 40

__global__ void __launch_bounds__(256) gemm_fb_kernel() {
    if (*(volatile int*)&g_fb == 0) return;
    __shared__ __nv_bfloat16 As[128 * ASTRIDE];
    __shared__ __nv_bfloat16 Bs[128 * ASTRIDE];
    __shared__ float rsum[2][128];

    const int tid = threadIdx.x;
    const int m0 = blockIdx.x * 128;
    const int n0 = blockIdx.y * 128;
    const int warp = tid >> 5, lane = tid & 31;
    const int mw = warp >> 1, nw = warp & 1;

    float acc[2][8][4];
#pragma unroll
    for (int a = 0; a < 2; a++)
#pragma unroll
        for (int b = 0; b < 8; b++)
#pragma unroll
            for (int c = 0; c < 4; c++) acc[a][b][c] = 0.f;

    uint2 pa[4], pb[4];
    auto loadG = [&](int kk) {
#pragma unroll
        for (int j = 0; j < 4; j++) {
            int i = tid + j * 256;
            int row = i >> 3, seg = i & 7;
            pa[j] = ld_blk8(g_X8, m0 + row, kk + seg * 4, 1.0f);
            pb[j] = ld_blk8(g_W8, n0 + row, kk + seg * 4, WISCALE);
        }
    };
    auto storeS = [&]() {
#pragma unroll
        for (int j = 0; j < 4; j++) {
            int i = tid + j * 256;
            int row = i >> 3, seg = i & 7;
            *reinterpret_cast<uint2*>(As + row * ASTRIDE + seg * 4) = pa[j];
            *reinterpret_cast<uint2*>(Bs + row * ASTRIDE + seg * 4) = pb[j];
        }
    };

    loadG(0);
    storeS();

    for (int it = 0; it < 128; ++it) {
        __syncthreads();
        if (it + 1 < 128) loadG((it + 1) * 32);

#pragma unroll
        for (int ks = 0; ks < 32; ks += 16) {
            uint32_t a[2][4];
#pragma unroll
            for (int mt = 0; mt < 2; mt++) {
                int row = mw * 32 + mt * 16 + (lane & 15);
                int col = ks + ((lane >> 4) << 3);
                uint32_t addr = smem_u32(As + row * ASTRIDE + col);
                asm volatile(
                    "ldmatrix.sync.aligned.m8n8.x4.shared.b16 {%0,%1,%2,%3}, [%4];"
                    : "=r"(a[mt][0]), "=r"(a[mt][1]), "=r"(a[mt][2]), "=r"(a[mt][3])
                    : "r"(addr));
            }
            uint32_t b[8][2];
#pragma unroll
            for (int np = 0; np < 4; np++) {
                int n = nw * 64 + np * 16 + (lane & 7) + ((lane >> 4) << 3);
                int kq = ks + (((lane >> 3) & 1) << 3);
                uint32_t addr = smem_u32(Bs + n * ASTRIDE + kq);
                asm volatile(
                    "ldmatrix.sync.aligned.m8n8.x4.shared.b16 {%0,%1,%2,%3}, [%4];"
                    : "=r"(b[2 * np][0]), "=r"(b[2 * np][1]),
                      "=r"(b[2 * np + 1][0]), "=r"(b[2 * np + 1][1])
                    : "r"(addr));
            }
#pragma unroll
            for (int mt = 0; mt < 2; mt++)
#pragma unroll
                for (int nt = 0; nt < 8; nt++) {
                    float* c = acc[mt][nt];
                    asm volatile(
                        "mma.sync.aligned.m16n8k16.row.col.f32.bf16.bf16.f32 "
                        "{%0,%1,%2,%3}, {%4,%5,%6,%7}, {%8,%9}, {%0,%1,%2,%3};"
                        : "+f"(c[0]), "+f"(c[1]), "+f"(c[2]), "+f"(c[3])
                        : "r"(a[mt][0]), "r"(a[mt][1]), "r"(a[mt][2]), "r"(a[mt][3]),
                          "r"(b[nt][0]), "r"(b[nt][1]));
                }
        }
        __syncthreads();
        if (it + 1 < 128) storeS();
    }

#pragma unroll
    for (int mt = 0; mt < 2; mt++) {
        float slo = 0.f, shi = 0.f;
#pragma unroll
        for (int nt = 0; nt < 8; nt++) {
            slo += __expf(acc[mt][nt][0]) + __expf(acc[mt][nt][1]);
            shi += __expf(acc[mt][nt][2]) + __expf(acc[mt][nt][3]);
        }
        slo += __shfl_xor_sync(0xFFFFFFFFu, slo, 1);
        slo += __shfl_xor_sync(0xFFFFFFFFu, slo, 2);
        shi += __shfl_xor_sync(0xFFFFFFFFu, shi, 1);
        shi += __shfl_xor_sync(0xFFFFFFFFu, shi, 2);
        if ((lane & 3) == 0) {
            int rr = mw * 32 + mt * 16 + (lane >> 2);
            rsum[nw][rr] = slo;
            rsum[nw][rr + 8] = shi;
        }
    }
    __syncthreads();
    if (tid < 128) {
        g_sumexp[(size_t)blockIdx.y * Mv + m0 + tid] = rsum[0][tid] + rsum[1][tid];
    }
}

// ---------------- per-token logp ----------------
__global__ void token_reduce_kernel(const int* __restrict__ tg) {
    int t = blockIdx.x * blockDim.x + threadIdx.x;
    if (t >= Mv) return;
    const int fb = g_fb;
    const int rows = fb ? NROWS : NTILE_TC;   // read exactly what was written
    float s = 0.f;
    for (int c = 0; c < rows; c++) s += g_sumexp[(size_t)c * Mv + t];
    if (fb == 0) s -= 256.0f;   // tcgen05 path: 256 zero-logit pad columns
    g_logp[t] = (tg[t] != IGNORE_INDEX) ? (g_tgt[t] - logf(s)) : 0.f;
}

// ---------------- final loss / outputs ----------------
__global__ void final_kernel(const int* __restrict__ tg, float* __restrict__ out) {
    __shared__ float red[256];
    __shared__ int redi[256];
    __shared__ float seq[8];
    __shared__ float xw[2];
    int tid = threadIdx.x;

    for (int s = 0; s < 8; s++) {
        float v = 0.f; int c = 0;
        for (int i = tid; i < Sv; i += 256) {
            int t = s * Sv + i;
            v += g_logp[t];
            c += (tg[t] != IGNORE_INDEX);
        }
        red[tid] = v; redi[tid] = c;
        __syncthreads();
        for (int o = 128; o; o >>= 1) {
            if (tid < o) { red[tid] += red[tid + o]; redi[tid] += redi[tid + o]; }
            __syncthreads();
        }
        if (tid == 0) seq[s] = red[0] / (float)redi[0];
        __syncthreads();
    }

    for (int h = 0; h < 2; h++) {
        float v = 0.f;
        for (int i = tid; i < 4 * Sv; i += 256) v += g_xdw[h * 4 * Sv + i];
        red[tid] = v;
        __syncthreads();
        for (int o = 128; o; o >>= 1) {
            if (tid < o) red[tid] += red[tid + o];
            __syncthreads();
        }
        if (tid == 0) xw[h] = red[0];
        __syncthreads();
    }

    if (tid == 0) {
        float loss = 0.f;
#pragma unroll
        for (int i = 0; i < 4; i++) {
            float z = 0.1f * (seq[i] - seq[4 + i]);
            float ls = fminf(z, 0.f) - log1pf(expf(-fabsf(z)));   // log_sigmoid(z)
            loss += -ls;
        }
        loss *= 0.25f;
        out[0] = loss;
#pragma unroll
        for (int i = 0; i < 8; i++) out[1 + i] = seq[i];
        const float denom = 4.0f * (float)Sv * (float)Vv;
        out[9] = xw[0] / denom;
        out[10] = xw[1] / denom;
        out[11] = 0.0f;
    }
}

// ---------------- launch ----------------
extern "C" void kernel_launch(void* const* d_in, const int* in_sizes, int n_in,
                              void* d_out, int out_size) {
    const float* x = nullptr;
    const float* W = nullptr;
    const int* tg = nullptr;
    for (int i = 0; i < n_in; i++) {
        if (in_sizes[i] == Vv * Hv) W = (const float*)d_in[i];
        else if (in_sizes[i] == Mv * Hv) x = (const float*)d_in[i];
        else if (in_sizes[i] == Mv) tg = (const int*)d_in[i];
    }
    float* out = (float*)d_out;

    cudaFuncSetAttribute(gemm_kernel, cudaFuncAttributeMaxDynamicSharedMemorySize, GEMM_SMEM);

    wpass3_kernel<<<dim3(32, 250), 256>>>(W);                 // 1
    convx3_kernel<<<dim3(32, 32), 256>>>(x);                  // 2 (+reset duties)
    wsum_reduce_kernel<<<16, 256>>>();                        // 3 (g_wsum before gemm)
    gemm_kernel<<<4 * NCLUSTERS, GTHREADS, GEMM_SMEM>>>(x, W, tg); // 4 (+in-GEMM target)
    target_fb_kernel<<<512, 256>>>(x, W, tg);                 // 5 (no-op if tcgen05 ran)
    gemm_fb_kernel<<<dim3(32, 250), 256>>>();                 // 6 (no-op if tcgen05 ran)
    token_reduce_kernel<<<32, 128>>>(tg);                     // 7
    final_kernel<<<1, 256>>>(tg, out);                        // 8
}